// round 4
// baseline (speedup 1.0000x reference)
#include <cuda_runtime.h>
#include <math.h>

#define Bsz 2
#define Ssz 2048
#define HIDsz 1024
#define Hsz 16
#define Dsz 64
#define Msz (Bsz*Ssz)
#define BHsz (Bsz*Hsz)

typedef unsigned long long ull;

// Packed fp32x2 helpers (Blackwell FFMA2 path)
__device__ __forceinline__ void fma2(ull& d, ull a, ull b) {
    asm("fma.rn.f32x2 %0, %1, %2, %0;" : "+l"(d) : "l"(a), "l"(b));
}
__device__ __forceinline__ ull pack2(float x, float y) {
    ull r; asm("mov.b64 %0, {%1, %2};" : "=l"(r) : "f"(x), "f"(y)); return r;
}
__device__ __forceinline__ float2 unpack2(ull v) {
    float2 r; asm("mov.b64 {%0, %1}, %2;" : "=f"(r.x), "=f"(r.y) : "l"(v)); return r;
}
__device__ __forceinline__ void mul2(ull& d, ull a) {
    asm("mul.rn.f32x2 %0, %0, %1;" : "+l"(d) : "l"(a));
}

// Scratch (device globals are the sanctioned scratch mechanism)
__device__ float g_q[(size_t)BHsz*Ssz*Dsz];      // [B,H,S,D], pre-scaled
__device__ float g_k[(size_t)BHsz*Ssz*Dsz];
__device__ float g_v[(size_t)BHsz*Ssz*Dsz];
__device__ float g_ao[(size_t)Bsz*Ssz*Hsz*Dsz]; // attention out in [B,S,H*D]
__device__ float g_m[(size_t)BHsz*Ssz];          // per-row softmax max
__device__ float g_inv[(size_t)BHsz*Ssz];        // per-row 1/sum
__device__ float g_dummy_out[(size_t)Bsz*Ssz*HIDsz];

// ---------------------------------------------------------------------------
// Kernel 1: fused QKV projection. C[M=4096, N=3072] = X * W^T + b.
// 128x128 tile, 256 threads, 8x8 micro-tile via FFMA2, BK=16.
// ---------------------------------------------------------------------------
__global__ void __launch_bounds__(256) qkv_kernel(
    const float* __restrict__ x,
    const float* __restrict__ qw, const float* __restrict__ qbias,
    const float* __restrict__ kw, const float* __restrict__ kbias,
    const float* __restrict__ vw, const float* __restrict__ vbias,
    const float* __restrict__ scaling)
{
    __shared__ float As[16][128];
    __shared__ float Bs[16][128];
    __shared__ float s_scale[64];

    const int tid = threadIdx.x;
    const int tx = tid & 15, ty = tid >> 4;
    const int mBase = blockIdx.y * 128;
    const int nBase = blockIdx.x * 128;      // 0..2943
    const int which = nBase >> 10;           // 0=q,1=k,2=v
    const int nLoc  = nBase & 1023;
    const float* W    = (which == 0) ? qw    : (which == 1) ? kw    : vw;
    const float* bias = (which == 0) ? qbias : (which == 1) ? kbias : vbias;

    if (tid < 64) {
        float sc = scaling[tid];
        float sp = (sc > 20.f) ? sc : log1pf(expf(sc));
        s_scale[tid] = sp * (1.442695040888963f * 0.125f);  // LOG2E / sqrt(64)
    }

    ull acc2[8][4] = {};   // [i][j-pair], each holds (c[i][2jp], c[i][2jp+1])

    for (int kt = 0; kt < HIDsz; kt += 16) {
        float4 a[2], b[2];
        #pragma unroll
        for (int u = 0; u < 2; ++u) {
            int idx = tid + u*256;
            int row = idx >> 2, c4 = (idx & 3) << 2;
            a[u] = *(const float4*)(x + (size_t)(mBase+row)*HIDsz + kt + c4);
            b[u] = *(const float4*)(W + (size_t)(nLoc +row)*HIDsz + kt + c4);
        }
        __syncthreads();
        #pragma unroll
        for (int u = 0; u < 2; ++u) {
            int idx = tid + u*256;
            int row = idx >> 2, c4 = (idx & 3) << 2;
            As[c4+0][row]=a[u].x; As[c4+1][row]=a[u].y; As[c4+2][row]=a[u].z; As[c4+3][row]=a[u].w;
            Bs[c4+0][row]=b[u].x; Bs[c4+1][row]=b[u].y; Bs[c4+2][row]=b[u].z; Bs[c4+3][row]=b[u].w;
        }
        __syncthreads();
        #pragma unroll
        for (int k = 0; k < 16; ++k) {
            float av[8];
            *(float4*)&av[0] = *(const float4*)&As[k][ty<<3];
            *(float4*)&av[4] = *(const float4*)&As[k][(ty<<3)+4];
            ulonglong2 b01 = *(const ulonglong2*)&Bs[k][tx<<3];
            ulonglong2 b23 = *(const ulonglong2*)&Bs[k][(tx<<3)+4];
            ull bv[4] = {b01.x, b01.y, b23.x, b23.y};
            #pragma unroll
            for (int i = 0; i < 8; ++i) {
                ull ad = pack2(av[i], av[i]);
                #pragma unroll
                for (int jp = 0; jp < 4; ++jp)
                    fma2(acc2[i][jp], ad, bv[jp]);
            }
        }
    }

    #pragma unroll
    for (int i = 0; i < 8; ++i) {
        int m = mBase + (ty<<3) + i;
        int b = m >> 11, s = m & (Ssz-1);
        #pragma unroll
        for (int jv = 0; jv < 2; ++jv) {
            int nl0 = nLoc + (tx<<3) + jv*4;
            int h = nl0 >> 6, d0 = nl0 & 63;
            size_t dst = (((size_t)(b*Hsz + h))*Ssz + s)*Dsz + d0;
            float2 p0 = unpack2(acc2[i][jv*2+0]);
            float2 p1 = unpack2(acc2[i][jv*2+1]);
            float vv[4] = {p0.x, p0.y, p1.x, p1.y};
            #pragma unroll
            for (int j = 0; j < 4; ++j) {
                vv[j] += bias[nl0 + j];
                if (which == 0) vv[j] *= s_scale[d0 + j];
            }
            float4 v4 = make_float4(vv[0],vv[1],vv[2],vv[3]);
            if (which == 0)      *(float4*)&g_q[dst] = v4;
            else if (which == 1) *(float4*)&g_k[dst] = v4;
            else                 *(float4*)&g_v[dst] = v4;
        }
    }
}

// ---------------------------------------------------------------------------
// Kernel 2: single-pass flash attention. 128-row q tile, 64-col k tiles.
// 256 threads, 8x4 micro-tile via FFMA2. Writes RAW scores to attn buffer
// (lower triangle), stats to g_m/g_inv, normalized O to g_ao.
// ---------------------------------------------------------------------------
__global__ void __launch_bounds__(256) attn_kernel(float* __restrict__ attnp)
{
    extern __shared__ float smem[];
    float* Qs   = smem;              // [d][r]  pitch 128
    float* Ks   = Qs + 64*128;       // [d][t]  pitch 64
    float* Vs   = Ks + 64*64;        // [t][d]  pitch 64
    float* Ps   = Vs + 64*64;        // [t][r]  pitch 132
    float* rmax = Ps + 64*132;       // [128]
    float* rsum = rmax + 128;        // [128]

    const int tid = threadIdx.x;
    const int tx = tid & 15, ty = tid >> 4;
    const int qb = (int)(gridDim.x - 1) - (int)blockIdx.x;  // heavy blocks first
    const int bh = blockIdx.y;
    const float* qBase = g_q + (size_t)bh * Ssz * Dsz;
    const float* kBase = g_k + (size_t)bh * Ssz * Dsz;
    const float* vBase = g_v + (size_t)bh * Ssz * Dsz;
    float* aBase = attnp ? (attnp + (size_t)bh * Ssz * Ssz) : (float*)0;

    // Load Q tile transposed to [d][r]
    #pragma unroll
    for (int u = 0; u < 8; ++u) {
        int idx = tid + u*256;
        int row = idx >> 4, c4 = (idx & 15) << 2;
        float4 v = *(const float4*)(qBase + (size_t)(qb*128 + row)*Dsz + c4);
        Qs[(c4+0)*128+row]=v.x; Qs[(c4+1)*128+row]=v.y; Qs[(c4+2)*128+row]=v.z; Qs[(c4+3)*128+row]=v.w;
    }
    if (tid < 128) { rmax[tid] = -INFINITY; rsum[tid] = 0.f; }

    ull oacc2[8][2] = {};     // packed O accumulators
    const int ntb = 2*qb + 2;

    for (int tb = 0; tb < ntb; ++tb) {
        float4 kv[4], vv4[4];
        #pragma unroll
        for (int u = 0; u < 4; ++u) {
            int idx = tid + u*256;
            int row = idx >> 4, c4 = (idx & 15) << 2;
            kv[u]  = *(const float4*)(kBase + (size_t)(tb*64 + row)*Dsz + c4);
            vv4[u] = *(const float4*)(vBase + (size_t)(tb*64 + row)*Dsz + c4);
        }
        __syncthreads();   // prior PV reads done
        #pragma unroll
        for (int u = 0; u < 4; ++u) {
            int idx = tid + u*256;
            int row = idx >> 4, c4 = (idx & 15) << 2;
            Ks[(c4+0)*64+row]=kv[u].x; Ks[(c4+1)*64+row]=kv[u].y; Ks[(c4+2)*64+row]=kv[u].z; Ks[(c4+3)*64+row]=kv[u].w;
            *(float4*)(Vs + row*64 + c4) = vv4[u];
        }
        __syncthreads();

        // ---- QK via FFMA2: sc2[8][2] ----
        ull sc2[8][2] = {};
        #pragma unroll 8
        for (int d = 0; d < 64; ++d) {
            float av[8];
            *(float4*)&av[0] = *(const float4*)(Qs + d*128 + (ty<<3));
            *(float4*)&av[4] = *(const float4*)(Qs + d*128 + (ty<<3) + 4);
            ulonglong2 bp = *(const ulonglong2*)(Ks + d*64 + (tx<<2));
            #pragma unroll
            for (int i = 0; i < 8; ++i) {
                ull ad = pack2(av[i], av[i]);
                fma2(sc2[i][0], ad, bp.x);
                fma2(sc2[i][1], ad, bp.y);
            }
        }

        // unpack scores
        float sc[8][4];
        #pragma unroll
        for (int i = 0; i < 8; ++i) {
            float2 s0 = unpack2(sc2[i][0]);
            float2 s1 = unpack2(sc2[i][1]);
            sc[i][0]=s0.x; sc[i][1]=s0.y; sc[i][2]=s1.x; sc[i][3]=s1.y;
        }
        if (tb >= 2*qb) {   // diagonal-overlapping tiles: causal mask
            #pragma unroll
            for (int i = 0; i < 8; ++i)
                #pragma unroll
                for (int j = 0; j < 4; ++j)
                    if (tb*64 + (tx<<2) + j > qb*128 + (ty<<3) + i)
                        sc[i][j] = -INFINITY;
        }

        // ---- online softmax stats + raw score write + Ps ----
        #pragma unroll
        for (int i = 0; i < 8; ++i) {
            int r = (ty<<3) + i;
            float mt = fmaxf(fmaxf(sc[i][0],sc[i][1]), fmaxf(sc[i][2],sc[i][3]));
            #pragma unroll
            for (int off = 8; off; off >>= 1)
                mt = fmaxf(mt, __shfl_xor_sync(0xffffffffu, mt, off, 16));
            float mo = rmax[r];
            float mn = fmaxf(mo, mt);
            float factor = expf(mo - mn);            // -inf -> 0 on first tile
            float p0 = expf(sc[i][0]-mn);
            float p1 = expf(sc[i][1]-mn);
            float p2 = expf(sc[i][2]-mn);
            float p3 = expf(sc[i][3]-mn);
            float st = p0+p1+p2+p3;
            #pragma unroll
            for (int off = 8; off; off >>= 1)
                st += __shfl_xor_sync(0xffffffffu, st, off, 16);
            ull f2 = pack2(factor, factor);
            mul2(oacc2[i][0], f2);
            mul2(oacc2[i][1], f2);
            Ps[((tx<<2)+0)*132 + r] = p0;
            Ps[((tx<<2)+1)*132 + r] = p1;
            Ps[((tx<<2)+2)*132 + r] = p2;
            Ps[((tx<<2)+3)*132 + r] = p3;
            if (aBase)
                *(float4*)(aBase + (size_t)(qb*128 + r)*Ssz + tb*64 + (tx<<2)) =
                    make_float4(sc[i][0], sc[i][1], sc[i][2], sc[i][3]);
            if (tx == 0) { rsum[r] = rsum[r]*factor + st; rmax[r] = mn; }
        }
        __syncthreads();

        // ---- PV accumulate (unnormalized) via FFMA2 ----
        #pragma unroll 8
        for (int t = 0; t < 64; ++t) {
            float pv[8];
            *(float4*)&pv[0] = *(const float4*)(Ps + t*132 + (ty<<3));
            *(float4*)&pv[4] = *(const float4*)(Ps + t*132 + (ty<<3) + 4);
            ulonglong2 bp = *(const ulonglong2*)(Vs + t*64 + (tx<<2));
            #pragma unroll
            for (int i = 0; i < 8; ++i) {
                ull ad = pack2(pv[i], pv[i]);
                fma2(oacc2[i][0], ad, bp.x);
                fma2(oacc2[i][1], ad, bp.y);
            }
        }
    }

    // Final normalize + write O to [B, S, H*D]
    const int b = bh >> 4, h = bh & 15;
    #pragma unroll
    for (int i = 0; i < 8; ++i) {
        int r = (ty<<3) + i;
        float inv = 1.0f / rsum[r];
        int s = qb*128 + r;
        float2 o0 = unpack2(oacc2[i][0]);
        float2 o1 = unpack2(oacc2[i][1]);
        *(float4*)&g_ao[((size_t)(b*Ssz + s))*HIDsz + h*64 + (tx<<2)] =
            make_float4(o0.x*inv, o0.y*inv, o1.x*inv, o1.y*inv);
    }
    if (tid < 128) {
        int s = qb*128 + tid;
        g_m[(size_t)bh*Ssz + s]   = rmax[tid];
        g_inv[(size_t)bh*Ssz + s] = 1.0f / rsum[tid];
    }
}

// ---------------------------------------------------------------------------
// Kernel 3: normalize attn in-place: p = exp(s - m) / sum below diagonal,
// zeros above. One block per (bh,row); 256 threads x 8 floats = 2048 cols.
// ---------------------------------------------------------------------------
__global__ void __launch_bounds__(256) norm_kernel(float* __restrict__ attnp)
{
    const int row = blockIdx.x;
    const int bh  = blockIdx.y;
    const float m   = g_m[(size_t)bh*Ssz + row];
    const float inv = g_inv[(size_t)bh*Ssz + row];
    float* rowp = attnp + ((size_t)bh*Ssz + row)*Ssz;
    const int c = threadIdx.x << 3;
    #pragma unroll
    for (int u = 0; u < 2; ++u) {
        int c0 = c + u*4;
        if (c0 > row) {
            *(float4*)(rowp + c0) = make_float4(0.f,0.f,0.f,0.f);
        } else {
            float4 s = *(const float4*)(rowp + c0);
            float4 p;
            p.x = expf(s.x - m) * inv;
            p.y = (c0+1 <= row) ? expf(s.y - m) * inv : 0.f;
            p.z = (c0+2 <= row) ? expf(s.z - m) * inv : 0.f;
            p.w = (c0+3 <= row) ? expf(s.w - m) * inv : 0.f;
            *(float4*)(rowp + c0) = p;
        }
    }
}

// ---------------------------------------------------------------------------
// Kernel 4: output projection. out[4096,1024] = AO * o_w^T + o_b. FFMA2.
// ---------------------------------------------------------------------------
__global__ void __launch_bounds__(256) oproj_kernel(
    const float* __restrict__ W, const float* __restrict__ bias,
    float* __restrict__ outp)
{
    __shared__ float As[16][128];
    __shared__ float Bs[16][128];

    const int tid = threadIdx.x;
    const int tx = tid & 15, ty = tid >> 4;
    const int mBase = blockIdx.y * 128;
    const int nBase = blockIdx.x * 128;

    ull acc2[8][4] = {};

    for (int kt = 0; kt < HIDsz; kt += 16) {
        float4 a[2], b[2];
        #pragma unroll
        for (int u = 0; u < 2; ++u) {
            int idx = tid + u*256;
            int row = idx >> 2, c4 = (idx & 3) << 2;
            a[u] = *(const float4*)(g_ao + (size_t)(mBase+row)*HIDsz + kt + c4);
            b[u] = *(const float4*)(W    + (size_t)(nBase+row)*HIDsz + kt + c4);
        }
        __syncthreads();
        #pragma unroll
        for (int u = 0; u < 2; ++u) {
            int idx = tid + u*256;
            int row = idx >> 2, c4 = (idx & 3) << 2;
            As[c4+0][row]=a[u].x; As[c4+1][row]=a[u].y; As[c4+2][row]=a[u].z; As[c4+3][row]=a[u].w;
            Bs[c4+0][row]=b[u].x; Bs[c4+1][row]=b[u].y; Bs[c4+2][row]=b[u].z; Bs[c4+3][row]=b[u].w;
        }
        __syncthreads();
        #pragma unroll
        for (int k = 0; k < 16; ++k) {
            float av[8];
            *(float4*)&av[0] = *(const float4*)&As[k][ty<<3];
            *(float4*)&av[4] = *(const float4*)&As[k][(ty<<3)+4];
            ulonglong2 b01 = *(const ulonglong2*)&Bs[k][tx<<3];
            ulonglong2 b23 = *(const ulonglong2*)&Bs[k][(tx<<3)+4];
            ull bv[4] = {b01.x, b01.y, b23.x, b23.y};
            #pragma unroll
            for (int i = 0; i < 8; ++i) {
                ull ad = pack2(av[i], av[i]);
                #pragma unroll
                for (int jp = 0; jp < 4; ++jp)
                    fma2(acc2[i][jp], ad, bv[jp]);
            }
        }
    }

    #pragma unroll
    for (int i = 0; i < 8; ++i) {
        int m = mBase + (ty<<3) + i;
        #pragma unroll
        for (int jv = 0; jv < 2; ++jv) {
            int n0 = nBase + (tx<<3) + jv*4;
            float2 p0 = unpack2(acc2[i][jv*2+0]);
            float2 p1 = unpack2(acc2[i][jv*2+1]);
            float4 v4 = make_float4(p0.x + bias[n0+0],
                                    p0.y + bias[n0+1],
                                    p1.x + bias[n0+2],
                                    p1.y + bias[n0+3]);
            *(float4*)(outp + (size_t)m*HIDsz + n0) = v4;
        }
    }
}

// ---------------------------------------------------------------------------
extern "C" void kernel_launch(void* const* d_in, const int* in_sizes, int n_in,
                              void* d_out, int out_size)
{
    const float* x       = (const float*)d_in[0];
    // d_in[1] = attention_mask: deterministic causal mask, applied analytically
    const float* scaling = (const float*)d_in[2];
    const float* qw = (const float*)d_in[3];
    const float* qb = (const float*)d_in[4];
    const float* kw = (const float*)d_in[5];
    const float* kb = (const float*)d_in[6];
    const float* vw = (const float*)d_in[7];
    const float* vb = (const float*)d_in[8];
    const float* ow = (const float*)d_in[9];
    const float* ob = (const float*)d_in[10];

    const long long OUT_N  = (long long)Bsz*Ssz*HIDsz;       //   4,194,304
    const long long ATTN_N = (long long)Bsz*Hsz*Ssz*Ssz;     // 134,217,728

    float* outp  = (float*)d_out;
    float* attnp = 0;
    if ((long long)out_size >= OUT_N + ATTN_N) {
        attnp = (float*)d_out + OUT_N;          // tuple (out, attn) flattened
    } else if ((long long)out_size == ATTN_N) { // attn-only fallback
        attnp = (float*)d_out;
        void* p = 0;
        cudaGetSymbolAddress(&p, g_dummy_out);
        outp = (float*)p;
    }

    cudaFuncSetAttribute(attn_kernel,
                         cudaFuncAttributeMaxDynamicSharedMemorySize, 100352);

    dim3 blk(256);
    qkv_kernel<<<dim3(24, 32), blk>>>(x, qw, qb, kw, kb, vw, vb, scaling);
    attn_kernel<<<dim3(Ssz/128, BHsz), blk, 100352>>>(attnp);
    if (attnp)
        norm_kernel<<<dim3(Ssz, BHsz), blk>>>(attnp);
    oproj_kernel<<<dim3(HIDsz/128, Msz/128), blk>>>(ow, ob, outp);
}

// round 7
// speedup vs baseline: 1.3826x; 1.3826x over previous
#include <cuda_runtime.h>
#include <cuda_bf16.h>
#include <math.h>
#include <stdint.h>

#define Bsz 2
#define Ssz 2048
#define HIDsz 1024
#define Hsz 16
#define Dsz 64
#define Msz (Bsz*Ssz)
#define BHsz (Bsz*Hsz)

// ---------------- scratch globals ----------------
__device__ float g_q[(size_t)BHsz*Ssz*Dsz];      // [B,H,S,D], pre-scaled
__device__ float g_k[(size_t)BHsz*Ssz*Dsz];
__device__ float g_v[(size_t)BHsz*Ssz*Dsz];
__device__ float g_ao[(size_t)Bsz*Ssz*Hsz*Dsz]; // attention out [B,S,H*D]
__device__ float g_m[(size_t)BHsz*Ssz];
__device__ float g_inv[(size_t)BHsz*Ssz];
__device__ float g_dummy_out[(size_t)Bsz*Ssz*HIDsz];

__device__ __nv_bfloat16 g_xh[(size_t)Msz*HIDsz],  g_xl[(size_t)Msz*HIDsz];
__device__ __nv_bfloat16 g_wh[(size_t)3*HIDsz*HIDsz], g_wl[(size_t)3*HIDsz*HIDsz];
__device__ __nv_bfloat16 g_owh[(size_t)HIDsz*HIDsz],  g_owl[(size_t)HIDsz*HIDsz];
__device__ __nv_bfloat16 g_aoh[(size_t)Msz*HIDsz], g_aol[(size_t)Msz*HIDsz];
__device__ float g_bqkv[3*HIDsz];
__device__ float g_scale[Dsz];

// ---------------- helpers ----------------
__device__ __forceinline__ uint32_t smem_u32(const void* p) {
    uint32_t a;
    asm("{ .reg .u64 t; cvta.to.shared.u64 t, %1; cvt.u32.u64 %0, t; }" : "=r"(a) : "l"(p));
    return a;
}
__device__ __forceinline__ void cp16(uint32_t dst, const void* src) {
    asm volatile("cp.async.cg.shared.global [%0], [%1], 16;" :: "r"(dst), "l"(src));
}
__device__ __forceinline__ void ldsm4(uint32_t* r, uint32_t a) {
    asm volatile("ldmatrix.sync.aligned.m8n8.x4.shared.b16 {%0,%1,%2,%3}, [%4];"
        : "=r"(r[0]), "=r"(r[1]), "=r"(r[2]), "=r"(r[3]) : "r"(a));
}
__device__ __forceinline__ void mma_bf16(float* c, const uint32_t* a, const uint32_t* b) {
    asm volatile("mma.sync.aligned.m16n8k16.row.col.f32.bf16.bf16.f32 "
        "{%0,%1,%2,%3}, {%4,%5,%6,%7}, {%8,%9}, {%0,%1,%2,%3};"
        : "+f"(c[0]), "+f"(c[1]), "+f"(c[2]), "+f"(c[3])
        : "r"(a[0]), "r"(a[1]), "r"(a[2]), "r"(a[3]), "r"(b[0]), "r"(b[1]));
}

// ---------------- prepack: fp32 -> bf16 hi/lo ----------------
struct alignas(8) B4 { __nv_bfloat16 v[4]; };

__global__ void __launch_bounds__(256) cvt_split_kernel(
    const float* __restrict__ src, __nv_bfloat16* __restrict__ hi,
    __nv_bfloat16* __restrict__ lo, int n4)
{
    int i = blockIdx.x * 256 + threadIdx.x;
    if (i >= n4) return;
    float4 x = ((const float4*)src)[i];
    B4 h, l;
    float xs[4] = {x.x, x.y, x.z, x.w};
    #pragma unroll
    for (int j = 0; j < 4; ++j) {
        __nv_bfloat16 hb = __float2bfloat16_rn(xs[j]);
        h.v[j] = hb;
        l.v[j] = __float2bfloat16_rn(xs[j] - __bfloat162float(hb));
    }
    *(B4*)(hi + 4*(size_t)i) = h;
    *(B4*)(lo + 4*(size_t)i) = l;
}

__global__ void pack_misc_kernel(const float* qb, const float* kb, const float* vb,
                                 const float* scaling)
{
    int i = blockIdx.x * 256 + threadIdx.x;
    if (i < 1024)       g_bqkv[i] = qb[i];
    else if (i < 2048)  g_bqkv[i] = kb[i-1024];
    else if (i < 3072)  g_bqkv[i] = vb[i-2048];
    if (i < 64) {
        float sc = scaling[i];
        float sp = (sc > 20.f) ? sc : log1pf(expf(sc));
        g_scale[i] = sp * (1.442695040888963f * 0.125f);
    }
}

// ---------------- HMMA GEMM mainloop ----------------
// 128x128 tile, 256 threads = 8 warps (2m x 4n), warp tile 64x32.
// K-chunk 32, 2-stage cp.async pipeline.
// smem per stage: 4 tiles (Ah, Al, Bh, Bl) of [128][PITCH=40] bf16.
#define PITCH   40
#define TILE_B  (128*PITCH*2)     // 10240
#define STAGE_B (4*TILE_B)        // 40960
#define GEMM_SMEM (2*STAGE_B)     // 81920

__device__ __forceinline__ void gemm128(
    uint32_t smem_base,
    const __nv_bfloat16* __restrict__ Ah, const __nv_bfloat16* __restrict__ Al,
    const __nv_bfloat16* __restrict__ Bh, const __nv_bfloat16* __restrict__ Bl,
    int mBase, int nBase, float acc[4][4][4])
{
    const int tid  = threadIdx.x;
    const int wid  = tid >> 5, lane = tid & 31;
    const int warpM = wid >> 2, warpN = wid & 3;

    // chunk loader: 512 x 16B per tile pair set (8 cp16 per thread)
    #define LOAD_CHUNK(ch) do {                                                 \
        const int st_ = (ch) & 1; const int kt_ = (ch) * 32;                    \
        uint32_t sb_ = smem_base + st_ * STAGE_B;                               \
        _Pragma("unroll")                                                       \
        for (int t_ = 0; t_ < 4; ++t_) {                                        \
            const __nv_bfloat16* src_ = t_==0?Ah:t_==1?Al:t_==2?Bh:Bl;          \
            int rowBase_ = (t_ < 2) ? mBase : nBase;                            \
            _Pragma("unroll")                                                   \
            for (int u_ = 0; u_ < 2; ++u_) {                                    \
                int idx_ = u_*256 + tid;                                        \
                int row_ = idx_ >> 2, cc_ = idx_ & 3;                           \
                cp16(sb_ + t_*TILE_B + row_*(PITCH*2) + cc_*16,                 \
                     src_ + (size_t)(rowBase_+row_)*HIDsz + kt_ + cc_*8);       \
            }                                                                   \
        }                                                                       \
        asm volatile("cp.async.commit_group;" ::: "memory");                    \
    } while (0)

    LOAD_CHUNK(0);
    for (int ch = 0; ch < 32; ++ch) {
        if (ch < 31) {
            LOAD_CHUNK(ch+1);
            asm volatile("cp.async.wait_group 1;" ::: "memory");
        } else {
            asm volatile("cp.async.wait_group 0;" ::: "memory");
        }
        __syncthreads();
        uint32_t sb = smem_base + (ch & 1) * STAGE_B;

        #pragma unroll
        for (int ks = 0; ks < 2; ++ks) {
            uint32_t ah[4][4], al[4][4], bh[2][4], bl[2][4];
            int acol = ks*32 + 16*(lane >> 4);
            int arow = warpM*64 + (lane & 15);
            #pragma unroll
            for (int mt = 0; mt < 4; ++mt)
                ldsm4(ah[mt], sb + 0*TILE_B + (arow + mt*16)*(PITCH*2) + acol);
            #pragma unroll
            for (int mt = 0; mt < 4; ++mt)
                ldsm4(al[mt], sb + 1*TILE_B + (arow + mt*16)*(PITCH*2) + acol);
            int bcol  = ks*32 + 16*((lane >> 3) & 1);
            int brow  = warpN*32 + (lane & 7) + ((lane >> 4) << 3);
            #pragma unroll
            for (int np = 0; np < 2; ++np) {
                ldsm4(bh[np], sb + 2*TILE_B + (brow + np*16)*(PITCH*2) + bcol);
                ldsm4(bl[np], sb + 3*TILE_B + (brow + np*16)*(PITCH*2) + bcol);
            }
            #pragma unroll
            for (int mt = 0; mt < 4; ++mt)
                #pragma unroll
                for (int nt = 0; nt < 4; ++nt) {
                    const uint32_t* bhp = &bh[nt >> 1][(nt & 1) * 2];
                    const uint32_t* blp = &bl[nt >> 1][(nt & 1) * 2];
                    mma_bf16(acc[mt][nt], ah[mt], bhp);
                    mma_bf16(acc[mt][nt], al[mt], bhp);
                    mma_bf16(acc[mt][nt], ah[mt], blp);
                }
        }
        __syncthreads();
    }
    #undef LOAD_CHUNK
}

// ---------------- QKV projection (HMMA) ----------------
__global__ void __launch_bounds__(256) qkv_mma_kernel()
{
    extern __shared__ char smem[];
    uint32_t smem_base = smem_u32(smem);
    const int tid = threadIdx.x;
    const int wid = tid >> 5, lane = tid & 31;
    const int warpM = wid >> 2, warpN = wid & 3;
    const int nBase = blockIdx.x * 128;   // 0..2943
    const int mBase = blockIdx.y * 128;

    float acc[4][4][4] = {};
    gemm128(smem_base, g_xh, g_xl, g_wh, g_wl, mBase, nBase, acc);

    const int which = nBase >> 10;
    float* dstBase = (which == 0) ? g_q : (which == 1) ? g_k : g_v;
    const int scaleQ = (which == 0);

    #pragma unroll
    for (int mt = 0; mt < 4; ++mt) {
        int m0 = mBase + warpM*64 + mt*16 + (lane >> 2);
        #pragma unroll
        for (int nt = 0; nt < 4; ++nt) {
            int nG = nBase + warpN*32 + nt*8 + 2*(lane & 3);
            int nl = nG & 1023, h = nl >> 6, d = nl & 63;
            float s0 = scaleQ ? g_scale[d] : 1.f, s1 = scaleQ ? g_scale[d+1] : 1.f;
            float b0 = g_bqkv[nG], b1 = g_bqkv[nG+1];
            #pragma unroll
            for (int half = 0; half < 2; ++half) {
                int m = m0 + half*8;
                int b = m >> 11, s = m & 2047;
                float v0 = (acc[mt][nt][half*2+0] + b0) * s0;
                float v1 = (acc[mt][nt][half*2+1] + b1) * s1;
                *(float2*)&dstBase[((size_t)(b*Hsz + h)*Ssz + s)*Dsz + d] =
                    make_float2(v0, v1);
            }
        }
    }
}

// ---------------- output projection (HMMA) ----------------
__global__ void __launch_bounds__(256) oproj_mma_kernel(
    const float* __restrict__ ob, float* __restrict__ outp)
{
    extern __shared__ char smem[];
    uint32_t smem_base = smem_u32(smem);
    const int tid = threadIdx.x;
    const int wid = tid >> 5, lane = tid & 31;
    const int warpM = wid >> 2, warpN = wid & 3;
    const int nBase = blockIdx.x * 128;
    const int mBase = blockIdx.y * 128;

    float acc[4][4][4] = {};
    gemm128(smem_base, g_aoh, g_aol, g_owh, g_owl, mBase, nBase, acc);

    #pragma unroll
    for (int mt = 0; mt < 4; ++mt) {
        int m0 = mBase + warpM*64 + mt*16 + (lane >> 2);
        #pragma unroll
        for (int nt = 0; nt < 4; ++nt) {
            int n = nBase + warpN*32 + nt*8 + 2*(lane & 3);
            float b0 = ob[n], b1 = ob[n+1];
            #pragma unroll
            for (int half = 0; half < 2; ++half) {
                int m = m0 + half*8;
                *(float2*)&outp[(size_t)m*HIDsz + n] = make_float2(
                    acc[mt][nt][half*2+0] + b0, acc[mt][nt][half*2+1] + b1);
            }
        }
    }
}

// ---------------- attention (R3 SIMT flash) ----------------
__global__ void __launch_bounds__(256) attn_kernel(float* __restrict__ attnp)
{
    extern __shared__ float smemf[];
    float* Qs   = smemf;             // [d][r] pitch 128
    float* Ks   = Qs + 64*128;       // [d][t] pitch 64
    float* Vs   = Ks + 64*64;        // [t][d] pitch 64
    float* Ps   = Vs + 64*64;        // [t][r] pitch 132
    float* rmax = Ps + 64*132;
    float* rsum = rmax + 128;

    const int tid = threadIdx.x;
    const int tx = tid & 15, ty = tid >> 4;
    const int qb = (int)(gridDim.x - 1) - (int)blockIdx.x;
    const int bh = blockIdx.y;
    const float* qBase = g_q + (size_t)bh * Ssz * Dsz;
    const float* kBase = g_k + (size_t)bh * Ssz * Dsz;
    const float* vBase = g_v + (size_t)bh * Ssz * Dsz;
    float* aBase = attnp ? (attnp + (size_t)bh * Ssz * Ssz) : (float*)0;

    #pragma unroll
    for (int u = 0; u < 8; ++u) {
        int idx = tid + u*256;
        int row = idx >> 4, c4 = (idx & 15) << 2;
        float4 v = *(const float4*)(qBase + (size_t)(qb*128 + row)*Dsz + c4);
        Qs[(c4+0)*128+row]=v.x; Qs[(c4+1)*128+row]=v.y; Qs[(c4+2)*128+row]=v.z; Qs[(c4+3)*128+row]=v.w;
    }
    if (tid < 128) { rmax[tid] = -INFINITY; rsum[tid] = 0.f; }

    float oacc[8][4] = {};
    const int ntb = 2*qb + 2;

    for (int tb = 0; tb < ntb; ++tb) {
        float4 kv[4], vv4[4];
        #pragma unroll
        for (int u = 0; u < 4; ++u) {
            int idx = tid + u*256;
            int row = idx >> 4, c4 = (idx & 15) << 2;
            kv[u]  = *(const float4*)(kBase + (size_t)(tb*64 + row)*Dsz + c4);
            vv4[u] = *(const float4*)(vBase + (size_t)(tb*64 + row)*Dsz + c4);
        }
        __syncthreads();
        #pragma unroll
        for (int u = 0; u < 4; ++u) {
            int idx = tid + u*256;
            int row = idx >> 4, c4 = (idx & 15) << 2;
            Ks[(c4+0)*64+row]=kv[u].x; Ks[(c4+1)*64+row]=kv[u].y; Ks[(c4+2)*64+row]=kv[u].z; Ks[(c4+3)*64+row]=kv[u].w;
            *(float4*)(Vs + row*64 + c4) = vv4[u];
        }
        __syncthreads();

        float sc[8][4];
        #pragma unroll
        for (int i = 0; i < 8; ++i)
            #pragma unroll
            for (int j = 0; j < 4; ++j) sc[i][j] = 0.f;
        #pragma unroll 8
        for (int d = 0; d < 64; ++d) {
            float av[8], bv[4];
            *(float4*)&av[0] = *(const float4*)(Qs + d*128 + (ty<<3));
            *(float4*)&av[4] = *(const float4*)(Qs + d*128 + (ty<<3) + 4);
            *(float4*)&bv[0] = *(const float4*)(Ks + d*64 + (tx<<2));
            #pragma unroll
            for (int i = 0; i < 8; ++i)
                #pragma unroll
                for (int j = 0; j < 4; ++j)
                    sc[i][j] = fmaf(av[i], bv[j], sc[i][j]);
        }
        if (tb >= 2*qb) {
            #pragma unroll
            for (int i = 0; i < 8; ++i)
                #pragma unroll
                for (int j = 0; j < 4; ++j)
                    if (tb*64 + (tx<<2) + j > qb*128 + (ty<<3) + i)
                        sc[i][j] = -INFINITY;
        }

        #pragma unroll
        for (int i = 0; i < 8; ++i) {
            int r = (ty<<3) + i;
            float mt = fmaxf(fmaxf(sc[i][0],sc[i][1]), fmaxf(sc[i][2],sc[i][3]));
            #pragma unroll
            for (int off = 8; off; off >>= 1)
                mt = fmaxf(mt, __shfl_xor_sync(0xffffffffu, mt, off, 16));
            float mo = rmax[r];
            float mn = fmaxf(mo, mt);
            float factor = expf(mo - mn);
            float p0 = expf(sc[i][0]-mn);
            float p1 = expf(sc[i][1]-mn);
            float p2 = expf(sc[i][2]-mn);
            float p3 = expf(sc[i][3]-mn);
            float st = p0+p1+p2+p3;
            #pragma unroll
            for (int off = 8; off; off >>= 1)
                st += __shfl_xor_sync(0xffffffffu, st, off, 16);
            oacc[i][0]*=factor; oacc[i][1]*=factor; oacc[i][2]*=factor; oacc[i][3]*=factor;
            Ps[((tx<<2)+0)*132 + r] = p0;
            Ps[((tx<<2)+1)*132 + r] = p1;
            Ps[((tx<<2)+2)*132 + r] = p2;
            Ps[((tx<<2)+3)*132 + r] = p3;
            if (aBase)
                *(float4*)(aBase + (size_t)(qb*128 + r)*Ssz + tb*64 + (tx<<2)) =
                    make_float4(sc[i][0], sc[i][1], sc[i][2], sc[i][3]);
            if (tx == 0) { rsum[r] = rsum[r]*factor + st; rmax[r] = mn; }
        }
        __syncthreads();

        #pragma unroll 8
        for (int t = 0; t < 64; ++t) {
            float pv[8], bv[4];
            *(float4*)&pv[0] = *(const float4*)(Ps + t*132 + (ty<<3));
            *(float4*)&pv[4] = *(const float4*)(Ps + t*132 + (ty<<3) + 4);
            *(float4*)&bv[0] = *(const float4*)(Vs + t*64 + (tx<<2));
            #pragma unroll
            for (int i = 0; i < 8; ++i)
                #pragma unroll
                for (int j = 0; j < 4; ++j)
                    oacc[i][j] = fmaf(pv[i], bv[j], oacc[i][j]);
        }
    }

    const int b = bh >> 4, h = bh & 15;
    #pragma unroll
    for (int i = 0; i < 8; ++i) {
        int r = (ty<<3) + i;
        float inv = 1.0f / rsum[r];
        int s = qb*128 + r;
        *(float4*)&g_ao[((size_t)(b*Ssz + s))*HIDsz + h*64 + (tx<<2)] =
            make_float4(oacc[i][0]*inv, oacc[i][1]*inv, oacc[i][2]*inv, oacc[i][3]*inv);
    }
    if (tid < 128) {
        int s = qb*128 + tid;
        g_m[(size_t)bh*Ssz + s]   = rmax[tid];
        g_inv[(size_t)bh*Ssz + s] = 1.0f / rsum[tid];
    }
}

// ---------------- normalize attn ----------------
__global__ void __launch_bounds__(256) norm_kernel(float* __restrict__ attnp)
{
    const int row = blockIdx.x;
    const int bh  = blockIdx.y;
    const float m   = g_m[(size_t)bh*Ssz + row];
    const float inv = g_inv[(size_t)bh*Ssz + row];
    float* rowp = attnp + ((size_t)bh*Ssz + row)*Ssz;
    const int c = threadIdx.x << 3;
    #pragma unroll
    for (int u = 0; u < 2; ++u) {
        int c0 = c + u*4;
        if (c0 > row) {
            *(float4*)(rowp + c0) = make_float4(0.f,0.f,0.f,0.f);
        } else {
            float4 s = *(const float4*)(rowp + c0);
            float4 p;
            p.x = expf(s.x - m) * inv;
            p.y = (c0+1 <= row) ? expf(s.y - m) * inv : 0.f;
            p.z = (c0+2 <= row) ? expf(s.z - m) * inv : 0.f;
            p.w = (c0+3 <= row) ? expf(s.w - m) * inv : 0.f;
            *(float4*)(rowp + c0) = p;
        }
    }
}

// ---------------- launch ----------------
extern "C" void kernel_launch(void* const* d_in, const int* in_sizes, int n_in,
                              void* d_out, int out_size)
{
    const float* x       = (const float*)d_in[0];
    const float* scaling = (const float*)d_in[2];
    const float* qw = (const float*)d_in[3];
    const float* qb = (const float*)d_in[4];
    const float* kw = (const float*)d_in[5];
    const float* kb = (const float*)d_in[6];
    const float* vw = (const float*)d_in[7];
    const float* vb = (const float*)d_in[8];
    const float* ow = (const float*)d_in[9];
    const float* ob = (const float*)d_in[10];

    const long long OUT_N  = (long long)Bsz*Ssz*HIDsz;
    const long long ATTN_N = (long long)Bsz*Hsz*Ssz*Ssz;

    float* outp  = (float*)d_out;
    float* attnp = 0;
    if ((long long)out_size >= OUT_N + ATTN_N) {
        attnp = (float*)d_out + OUT_N;
    } else if ((long long)out_size == ATTN_N) {
        attnp = (float*)d_out;
        void* p = 0;
        cudaGetSymbolAddress(&p, g_dummy_out);
        outp = (float*)p;
    }

    cudaFuncSetAttribute(attn_kernel, cudaFuncAttributeMaxDynamicSharedMemorySize, 100352);
    cudaFuncSetAttribute(qkv_mma_kernel, cudaFuncAttributeMaxDynamicSharedMemorySize, GEMM_SMEM);
    cudaFuncSetAttribute(oproj_mma_kernel, cudaFuncAttributeMaxDynamicSharedMemorySize, GEMM_SMEM);

    void *xh, *xl, *wh, *wl, *owh_p, *owl_p, *aoh, *aol, *aop;
    cudaGetSymbolAddress(&xh, g_xh);   cudaGetSymbolAddress(&xl, g_xl);
    cudaGetSymbolAddress(&wh, g_wh);   cudaGetSymbolAddress(&wl, g_wl);
    cudaGetSymbolAddress(&owh_p, g_owh); cudaGetSymbolAddress(&owl_p, g_owl);
    cudaGetSymbolAddress(&aoh, g_aoh); cudaGetSymbolAddress(&aol, g_aol);
    cudaGetSymbolAddress(&aop, g_ao);

    const int N4_X = Msz*HIDsz/4;
    const int N4_W = HIDsz*HIDsz/4;

    cvt_split_kernel<<<(N4_X+255)/256, 256>>>(x, (__nv_bfloat16*)xh, (__nv_bfloat16*)xl, N4_X);
    cvt_split_kernel<<<(N4_W+255)/256, 256>>>(qw, (__nv_bfloat16*)wh, (__nv_bfloat16*)wl, N4_W);
    cvt_split_kernel<<<(N4_W+255)/256, 256>>>(kw, (__nv_bfloat16*)wh + (size_t)HIDsz*HIDsz,
                                              (__nv_bfloat16*)wl + (size_t)HIDsz*HIDsz, N4_W);
    cvt_split_kernel<<<(N4_W+255)/256, 256>>>(vw, (__nv_bfloat16*)wh + 2*(size_t)HIDsz*HIDsz,
                                              (__nv_bfloat16*)wl + 2*(size_t)HIDsz*HIDsz, N4_W);
    cvt_split_kernel<<<(N4_W+255)/256, 256>>>(ow, (__nv_bfloat16*)owh_p, (__nv_bfloat16*)owl_p, N4_W);
    pack_misc_kernel<<<12, 256>>>(qb, kb, vb, scaling);

    qkv_mma_kernel<<<dim3(24, 32), 256, GEMM_SMEM>>>();

    attn_kernel<<<dim3(Ssz/128, BHsz), 256, 100352>>>(attnp);
    if (attnp)
        norm_kernel<<<dim3(Ssz, BHsz), 256>>>(attnp);

    cvt_split_kernel<<<(N4_X+255)/256, 256>>>((const float*)aop,
                                              (__nv_bfloat16*)aoh, (__nv_bfloat16*)aol, N4_X);
    oproj_mma_kernel<<<dim3(HIDsz/128, Msz/128), 256, GEMM_SMEM>>>(ob, outp);
}

// round 8
// speedup vs baseline: 2.3784x; 1.7202x over previous
#include <cuda_runtime.h>
#include <cuda_bf16.h>
#include <math.h>
#include <stdint.h>

#define Bsz 2
#define Ssz 2048
#define HIDsz 1024
#define Hsz 16
#define Dsz 64
#define Msz (Bsz*Ssz)
#define BHsz (Bsz*Hsz)

// ---------------- scratch globals ----------------
__device__ float g_v[(size_t)BHsz*Ssz*Dsz];      // [B,H,S,D] fp32 (for transpose)
__device__ float g_ao[(size_t)Bsz*Ssz*Hsz*Dsz]; // attention out [B,S,H*D]
__device__ float g_m[(size_t)BHsz*Ssz];
__device__ float g_inv[(size_t)BHsz*Ssz];
__device__ float g_dummy_out[(size_t)Bsz*Ssz*HIDsz];

__device__ __nv_bfloat16 g_qh[(size_t)BHsz*Ssz*Dsz], g_ql[(size_t)BHsz*Ssz*Dsz];
__device__ __nv_bfloat16 g_kh[(size_t)BHsz*Ssz*Dsz], g_kl[(size_t)BHsz*Ssz*Dsz];
__device__ __nv_bfloat16 g_vth[(size_t)BHsz*Dsz*Ssz], g_vtl[(size_t)BHsz*Dsz*Ssz]; // [bh][d][t]

__device__ __nv_bfloat16 g_xh[(size_t)Msz*HIDsz],  g_xl[(size_t)Msz*HIDsz];
__device__ __nv_bfloat16 g_wh[(size_t)3*HIDsz*HIDsz], g_wl[(size_t)3*HIDsz*HIDsz];
__device__ __nv_bfloat16 g_owh[(size_t)HIDsz*HIDsz],  g_owl[(size_t)HIDsz*HIDsz];
__device__ __nv_bfloat16 g_aoh[(size_t)Msz*HIDsz], g_aol[(size_t)Msz*HIDsz];
__device__ float g_bqkv[3*HIDsz];
__device__ float g_scale[Dsz];

// ---------------- helpers ----------------
__device__ __forceinline__ uint32_t smem_u32(const void* p) {
    uint32_t a;
    asm("{ .reg .u64 t; cvta.to.shared.u64 t, %1; cvt.u32.u64 %0, t; }" : "=r"(a) : "l"(p));
    return a;
}
__device__ __forceinline__ void cp16(uint32_t dst, const void* src) {
    asm volatile("cp.async.cg.shared.global [%0], [%1], 16;" :: "r"(dst), "l"(src));
}
__device__ __forceinline__ void ldsm4(uint32_t* r, uint32_t a) {
    asm volatile("ldmatrix.sync.aligned.m8n8.x4.shared.b16 {%0,%1,%2,%3}, [%4];"
        : "=r"(r[0]), "=r"(r[1]), "=r"(r[2]), "=r"(r[3]) : "r"(a));
}
__device__ __forceinline__ void mma_bf16(float* c, const uint32_t* a, const uint32_t* b) {
    asm volatile("mma.sync.aligned.m16n8k16.row.col.f32.bf16.bf16.f32 "
        "{%0,%1,%2,%3}, {%4,%5,%6,%7}, {%8,%9}, {%0,%1,%2,%3};"
        : "+f"(c[0]), "+f"(c[1]), "+f"(c[2]), "+f"(c[3])
        : "r"(a[0]), "r"(a[1]), "r"(a[2]), "r"(a[3]), "r"(b[0]), "r"(b[1]));
}
// pack two fp32 into bf16x2: low half <- lo, high half <- hi
__device__ __forceinline__ uint32_t pack_bf16x2(float lo, float hi) {
    uint32_t r; asm("cvt.rn.bf16x2.f32 %0, %1, %2;" : "=r"(r) : "f"(hi), "f"(lo)); return r;
}
__device__ __forceinline__ float2 bf16x2_to_f2(uint32_t u) {
    float2 r;
    r.x = __uint_as_float(u << 16);
    r.y = __uint_as_float(u & 0xffff0000u);
    return r;
}

// ---------------- prepack: fp32 -> bf16 hi/lo ----------------
struct alignas(8) B4 { __nv_bfloat16 v[4]; };

__global__ void __launch_bounds__(256) cvt_split_kernel(
    const float* __restrict__ src, __nv_bfloat16* __restrict__ hi,
    __nv_bfloat16* __restrict__ lo, int n4)
{
    int i = blockIdx.x * 256 + threadIdx.x;
    if (i >= n4) return;
    float4 x = ((const float4*)src)[i];
    B4 h, l;
    float xs[4] = {x.x, x.y, x.z, x.w};
    #pragma unroll
    for (int j = 0; j < 4; ++j) {
        __nv_bfloat16 hb = __float2bfloat16_rn(xs[j]);
        h.v[j] = hb;
        l.v[j] = __float2bfloat16_rn(xs[j] - __bfloat162float(hb));
    }
    *(B4*)(hi + 4*(size_t)i) = h;
    *(B4*)(lo + 4*(size_t)i) = l;
}

__global__ void pack_misc_kernel(const float* qb, const float* kb, const float* vb,
                                 const float* scaling)
{
    int i = blockIdx.x * 256 + threadIdx.x;
    if (i < 1024)       g_bqkv[i] = qb[i];
    else if (i < 2048)  g_bqkv[i] = kb[i-1024];
    else if (i < 3072)  g_bqkv[i] = vb[i-2048];
    if (i < 64) {
        float sc = scaling[i];
        float sp = (sc > 20.f) ? sc : log1pf(expf(sc));
        g_scale[i] = sp * (1.442695040888963f * 0.125f);
    }
}

// ---------------- HMMA GEMM mainloop (dense projections) ----------------
#define PITCH   40
#define TILE_B  (128*PITCH*2)
#define STAGE_B (4*TILE_B)
#define GEMM_SMEM (2*STAGE_B)

__device__ __forceinline__ void gemm128(
    uint32_t smem_base,
    const __nv_bfloat16* __restrict__ Ah, const __nv_bfloat16* __restrict__ Al,
    const __nv_bfloat16* __restrict__ Bh, const __nv_bfloat16* __restrict__ Bl,
    int mBase, int nBase, float acc[4][4][4])
{
    const int tid  = threadIdx.x;
    const int wid  = tid >> 5, lane = tid & 31;
    const int warpM = wid >> 2, warpN = wid & 3;

    #define LOAD_CHUNK(ch) do {                                                 \
        const int st_ = (ch) & 1; const int kt_ = (ch) * 32;                    \
        uint32_t sb_ = smem_base + st_ * STAGE_B;                               \
        _Pragma("unroll")                                                       \
        for (int t_ = 0; t_ < 4; ++t_) {                                        \
            const __nv_bfloat16* src_ = t_==0?Ah:t_==1?Al:t_==2?Bh:Bl;          \
            int rowBase_ = (t_ < 2) ? mBase : nBase;                            \
            _Pragma("unroll")                                                   \
            for (int u_ = 0; u_ < 2; ++u_) {                                    \
                int idx_ = u_*256 + tid;                                        \
                int row_ = idx_ >> 2, cc_ = idx_ & 3;                           \
                cp16(sb_ + t_*TILE_B + row_*(PITCH*2) + cc_*16,                 \
                     src_ + (size_t)(rowBase_+row_)*HIDsz + kt_ + cc_*8);       \
            }                                                                   \
        }                                                                       \
        asm volatile("cp.async.commit_group;" ::: "memory");                    \
    } while (0)

    LOAD_CHUNK(0);
    for (int ch = 0; ch < 32; ++ch) {
        if (ch < 31) {
            LOAD_CHUNK(ch+1);
            asm volatile("cp.async.wait_group 1;" ::: "memory");
        } else {
            asm volatile("cp.async.wait_group 0;" ::: "memory");
        }
        __syncthreads();
        uint32_t sb = smem_base + (ch & 1) * STAGE_B;

        #pragma unroll
        for (int ks = 0; ks < 2; ++ks) {
            uint32_t ah[4][4], al[4][4], bh[2][4], bl[2][4];
            int acol = ks*32 + 16*(lane >> 4);
            int arow = warpM*64 + (lane & 15);
            #pragma unroll
            for (int mt = 0; mt < 4; ++mt)
                ldsm4(ah[mt], sb + 0*TILE_B + (arow + mt*16)*(PITCH*2) + acol);
            #pragma unroll
            for (int mt = 0; mt < 4; ++mt)
                ldsm4(al[mt], sb + 1*TILE_B + (arow + mt*16)*(PITCH*2) + acol);
            int bcol  = ks*32 + 16*((lane >> 3) & 1);
            int brow  = warpN*32 + (lane & 7) + ((lane >> 4) << 3);
            #pragma unroll
            for (int np = 0; np < 2; ++np) {
                ldsm4(bh[np], sb + 2*TILE_B + (brow + np*16)*(PITCH*2) + bcol);
                ldsm4(bl[np], sb + 3*TILE_B + (brow + np*16)*(PITCH*2) + bcol);
            }
            #pragma unroll
            for (int mt = 0; mt < 4; ++mt)
                #pragma unroll
                for (int nt = 0; nt < 4; ++nt) {
                    const uint32_t* bhp = &bh[nt >> 1][(nt & 1) * 2];
                    const uint32_t* blp = &bl[nt >> 1][(nt & 1) * 2];
                    mma_bf16(acc[mt][nt], ah[mt], bhp);
                    mma_bf16(acc[mt][nt], al[mt], bhp);
                    mma_bf16(acc[mt][nt], ah[mt], blp);
                }
        }
        __syncthreads();
    }
    #undef LOAD_CHUNK
}

// ---------------- QKV projection (HMMA) ----------------
__global__ void __launch_bounds__(256) qkv_mma_kernel()
{
    extern __shared__ char smem[];
    uint32_t smem_base = smem_u32(smem);
    const int tid = threadIdx.x;
    const int wid = tid >> 5, lane = tid & 31;
    const int warpM = wid >> 2, warpN = wid & 3;
    const int nBase = blockIdx.x * 128;
    const int mBase = blockIdx.y * 128;

    float acc[4][4][4] = {};
    gemm128(smem_base, g_xh, g_xl, g_wh, g_wl, mBase, nBase, acc);

    const int which = nBase >> 10;

    #pragma unroll
    for (int mt = 0; mt < 4; ++mt) {
        int m0 = mBase + warpM*64 + mt*16 + (lane >> 2);
        #pragma unroll
        for (int nt = 0; nt < 4; ++nt) {
            int nG = nBase + warpN*32 + nt*8 + 2*(lane & 3);
            int nl = nG & 1023, h = nl >> 6, d = nl & 63;
            float s0 = (which == 0) ? g_scale[d] : 1.f;
            float s1 = (which == 0) ? g_scale[d+1] : 1.f;
            float b0 = g_bqkv[nG], b1 = g_bqkv[nG+1];
            #pragma unroll
            for (int half = 0; half < 2; ++half) {
                int m = m0 + half*8;
                int b = m >> 11, s = m & 2047;
                float v0 = (acc[mt][nt][half*2+0] + b0) * s0;
                float v1 = (acc[mt][nt][half*2+1] + b1) * s1;
                size_t off = ((size_t)(b*Hsz + h)*Ssz + s)*Dsz + d;
                if (which == 2) {
                    *(float2*)&g_v[off] = make_float2(v0, v1);
                } else {
                    uint32_t hh = pack_bf16x2(v0, v1);
                    float2 bb = bf16x2_to_f2(hh);
                    uint32_t ll = pack_bf16x2(v0 - bb.x, v1 - bb.y);
                    if (which == 0) {
                        *(uint32_t*)&g_qh[off] = hh;
                        *(uint32_t*)&g_ql[off] = ll;
                    } else {
                        *(uint32_t*)&g_kh[off] = hh;
                        *(uint32_t*)&g_kl[off] = ll;
                    }
                }
            }
        }
    }
}

// ---------------- V transpose + split: [bh][t][d] fp32 -> [bh][d][t] bf16 h/l
__global__ void __launch_bounds__(256) vt_cvt_kernel()
{
    __shared__ float ts[128][65];
    const int bh = blockIdx.y, tB = blockIdx.x, tid = threadIdx.x;
    const float* src = g_v + ((size_t)bh*Ssz + tB*128)*Dsz;
    #pragma unroll
    for (int u = 0; u < 8; ++u) {
        int idx = u*256 + tid;
        int row = idx >> 4, c4 = (idx & 15) << 2;
        float4 v = *(const float4*)(src + row*64 + c4);
        ts[row][c4]=v.x; ts[row][c4+1]=v.y; ts[row][c4+2]=v.z; ts[row][c4+3]=v.w;
    }
    __syncthreads();
    #pragma unroll
    for (int u = 0; u < 16; ++u) {
        int idx = u*256 + tid;           // 4096 bf16x2 pairs
        int d = idx >> 6, tp = idx & 63;
        float f0 = ts[tp*2][d], f1 = ts[tp*2+1][d];
        uint32_t h = pack_bf16x2(f0, f1);
        float2 hb = bf16x2_to_f2(h);
        uint32_t l = pack_bf16x2(f0 - hb.x, f1 - hb.y);
        size_t off = ((size_t)bh*Dsz + d)*Ssz + tB*128 + tp*2;
        *(uint32_t*)&g_vth[off] = h;
        *(uint32_t*)&g_vtl[off] = l;
    }
}

// ---------------- HMMA flash attention ----------------
// Per CTA: 128 q rows (8 warps x 16 rows), k tiles of 128. 2-stage cp.async.
// smem: Qh/Ql [128][72] bf16 + 2 stages of {Kh,Kl [128][72], Vth,Vtl [64][136]}
#define QH_OFF 0
#define QL_OFF 18432
#define ST_OFF 36864
#define ST_STRIDE 71680
#define KH_OFF 0
#define KL_OFF 18432
#define VH_OFF 36864
#define VL_OFF 54272
#define ATTN_SMEM 180224

__global__ void __launch_bounds__(256) attn_mma_kernel(float* __restrict__ attnp)
{
    extern __shared__ char sm[];
    const uint32_t sb = smem_u32(sm);
    const int tid = threadIdx.x, wid = tid >> 5, lane = tid & 31;
    const int gid = lane >> 2, qc = lane & 3;
    const int qb = (int)(gridDim.x - 1) - (int)blockIdx.x;   // heavy first
    const int bh = blockIdx.y;
    const int qrow0 = qb * 128;

    const __nv_bfloat16* qhg = g_qh + ((size_t)bh*Ssz + qrow0)*Dsz;
    const __nv_bfloat16* qlg = g_ql + ((size_t)bh*Ssz + qrow0)*Dsz;
    const __nv_bfloat16* khg = g_kh + (size_t)bh*Ssz*Dsz;
    const __nv_bfloat16* klg = g_kl + (size_t)bh*Ssz*Dsz;
    const __nv_bfloat16* vhg = g_vth + (size_t)bh*Dsz*Ssz;
    const __nv_bfloat16* vlg = g_vtl + (size_t)bh*Dsz*Ssz;
    float* aBase = attnp ? (attnp + (size_t)bh*Ssz*Ssz) : (float*)0;

    // Q tile + k/v tile 0 loads
    #pragma unroll
    for (int u = 0; u < 4; ++u) {
        int idx = u*256 + tid, row = idx >> 3, c = idx & 7;
        cp16(sb + QH_OFF + row*144 + c*16, qhg + (size_t)row*64 + c*8);
        cp16(sb + QL_OFF + row*144 + c*16, qlg + (size_t)row*64 + c*8);
    }
    {
        const uint32_t b0 = sb + ST_OFF;
        #pragma unroll
        for (int u = 0; u < 4; ++u) {
            int idx = u*256 + tid, row = idx >> 3, c = idx & 7;
            cp16(b0 + KH_OFF + row*144 + c*16, khg + (size_t)row*64 + c*8);
            cp16(b0 + KL_OFF + row*144 + c*16, klg + (size_t)row*64 + c*8);
        }
        #pragma unroll
        for (int u = 0; u < 4; ++u) {
            int idx = u*256 + tid, d = idx >> 4, c = idx & 15;
            cp16(b0 + VH_OFF + d*272 + c*16, vhg + (size_t)d*Ssz + c*8);
            cp16(b0 + VL_OFF + d*272 + c*16, vlg + (size_t)d*Ssz + c*8);
        }
    }
    asm volatile("cp.async.commit_group;" ::: "memory");

    float accO[8][4] = {};
    float rm0 = -INFINITY, rm1 = -INFINITY, rs0 = 0.f, rs1 = 0.f;
    uint32_t qfh[4][4], qfl[4][4];

    for (int tb = 0; tb <= qb; ++tb) {
        if (tb < qb) {
            const uint32_t bs2 = sb + ST_OFF + ((tb+1) & 1) * ST_STRIDE;
            const int t0 = (tb+1) * 128;
            #pragma unroll
            for (int u = 0; u < 4; ++u) {
                int idx = u*256 + tid, row = idx >> 3, c = idx & 7;
                cp16(bs2 + KH_OFF + row*144 + c*16, khg + (size_t)(t0+row)*64 + c*8);
                cp16(bs2 + KL_OFF + row*144 + c*16, klg + (size_t)(t0+row)*64 + c*8);
            }
            #pragma unroll
            for (int u = 0; u < 4; ++u) {
                int idx = u*256 + tid, d = idx >> 4, c = idx & 15;
                cp16(bs2 + VH_OFF + d*272 + c*16, vhg + (size_t)d*Ssz + t0 + c*8);
                cp16(bs2 + VL_OFF + d*272 + c*16, vlg + (size_t)d*Ssz + t0 + c*8);
            }
            asm volatile("cp.async.commit_group;" ::: "memory");
            asm volatile("cp.async.wait_group 1;" ::: "memory");
        } else {
            asm volatile("cp.async.wait_group 0;" ::: "memory");
        }
        __syncthreads();

        if (tb == 0) {
            #pragma unroll
            for (int ks = 0; ks < 4; ++ks) {
                uint32_t a = sb + QH_OFF + (wid*16 + (lane & 15))*144 + ks*32 + 16*(lane >> 4);
                ldsm4(qfh[ks], a);
                ldsm4(qfl[ks], a + (QL_OFF - QH_OFF));
            }
        }
        const uint32_t bs = sb + ST_OFF + (tb & 1) * ST_STRIDE;

        // ---- S = Q K^T (split bf16, fp32 acc) ----
        float accS[16][4];
        #pragma unroll
        for (int nt = 0; nt < 16; ++nt)
            accS[nt][0] = accS[nt][1] = accS[nt][2] = accS[nt][3] = 0.f;

        #pragma unroll
        for (int ks = 0; ks < 4; ++ks) {
            #pragma unroll
            for (int nh = 0; nh < 2; ++nh) {
                uint32_t kfh[4][4], kfl[4][4];
                #pragma unroll
                for (int t4 = 0; t4 < 4; ++t4) {
                    uint32_t addr = bs + KH_OFF
                        + (nh*64 + t4*16 + (lane & 7) + ((lane >> 4) << 3))*144
                        + ks*32 + 16*((lane >> 3) & 1);
                    ldsm4(kfh[t4], addr);
                    ldsm4(kfl[t4], addr + (KL_OFF - KH_OFF));
                }
                #pragma unroll
                for (int t4 = 0; t4 < 4; ++t4)
                    #pragma unroll
                    for (int sub = 0; sub < 2; ++sub) {
                        int nt = nh*8 + t4*2 + sub;
                        mma_bf16(accS[nt], qfh[ks], &kfh[t4][sub*2]);
                        mma_bf16(accS[nt], qfl[ks], &kfh[t4][sub*2]);
                        mma_bf16(accS[nt], qfh[ks], &kfl[t4][sub*2]);
                    }
            }
        }

        // raw score write (norm_kernel re-normalizes + zeroes upper triangle)
        if (aBase) {
            float* rp0 = aBase + (size_t)(qrow0 + wid*16 + gid)*Ssz + tb*128;
            float* rp1 = rp0 + (size_t)8*Ssz;
            #pragma unroll
            for (int nt = 0; nt < 16; ++nt) {
                int col = nt*8 + qc*2;
                *(float2*)(rp0 + col) = make_float2(accS[nt][0], accS[nt][1]);
                *(float2*)(rp1 + col) = make_float2(accS[nt][2], accS[nt][3]);
            }
        }
        if (tb == qb) {   // causal mask inside diagonal tile
            int rl0 = wid*16 + gid, rl1 = rl0 + 8;
            #pragma unroll
            for (int nt = 0; nt < 16; ++nt) {
                int c0 = nt*8 + qc*2;
                if (c0     > rl0) accS[nt][0] = -INFINITY;
                if (c0 + 1 > rl0) accS[nt][1] = -INFINITY;
                if (c0     > rl1) accS[nt][2] = -INFINITY;
                if (c0 + 1 > rl1) accS[nt][3] = -INFINITY;
            }
        }

        // ---- online softmax stats (per-warp rows, quad reduce) ----
        float m0 = -INFINITY, m1 = -INFINITY;
        #pragma unroll
        for (int nt = 0; nt < 16; ++nt) {
            m0 = fmaxf(m0, fmaxf(accS[nt][0], accS[nt][1]));
            m1 = fmaxf(m1, fmaxf(accS[nt][2], accS[nt][3]));
        }
        m0 = fmaxf(m0, __shfl_xor_sync(0xffffffffu, m0, 1));
        m0 = fmaxf(m0, __shfl_xor_sync(0xffffffffu, m0, 2));
        m1 = fmaxf(m1, __shfl_xor_sync(0xffffffffu, m1, 1));
        m1 = fmaxf(m1, __shfl_xor_sync(0xffffffffu, m1, 2));
        float nm0 = fmaxf(rm0, m0), nm1 = fmaxf(rm1, m1);
        float f0 = expf(rm0 - nm0), f1 = expf(rm1 - nm1);
        float s0 = 0.f, s1 = 0.f;
        #pragma unroll
        for (int nt = 0; nt < 16; ++nt) {
            accS[nt][0] = expf(accS[nt][0] - nm0);
            accS[nt][1] = expf(accS[nt][1] - nm0);
            accS[nt][2] = expf(accS[nt][2] - nm1);
            accS[nt][3] = expf(accS[nt][3] - nm1);
            s0 += accS[nt][0] + accS[nt][1];
            s1 += accS[nt][2] + accS[nt][3];
        }
        s0 += __shfl_xor_sync(0xffffffffu, s0, 1);
        s0 += __shfl_xor_sync(0xffffffffu, s0, 2);
        s1 += __shfl_xor_sync(0xffffffffu, s1, 1);
        s1 += __shfl_xor_sync(0xffffffffu, s1, 2);
        rs0 = rs0*f0 + s0;  rs1 = rs1*f1 + s1;
        rm0 = nm0;          rm1 = nm1;
        #pragma unroll
        for (int nd = 0; nd < 8; ++nd) {
            accO[nd][0] *= f0; accO[nd][1] *= f0;
            accO[nd][2] *= f1; accO[nd][3] *= f1;
        }

        // ---- O += P V (P re-packed C->A frags in registers, split) ----
        #pragma unroll
        for (int j = 0; j < 8; ++j) {
            uint32_t pah[4], pal[4];
            {
                float c0 = accS[2*j][0],   c1 = accS[2*j][1];
                float c2 = accS[2*j][2],   c3 = accS[2*j][3];
                float d0 = accS[2*j+1][0], d1 = accS[2*j+1][1];
                float d2 = accS[2*j+1][2], d3 = accS[2*j+1][3];
                pah[0] = pack_bf16x2(c0, c1);  pah[1] = pack_bf16x2(c2, c3);
                pah[2] = pack_bf16x2(d0, d1);  pah[3] = pack_bf16x2(d2, d3);
                float2 bb;
                bb = bf16x2_to_f2(pah[0]); pal[0] = pack_bf16x2(c0-bb.x, c1-bb.y);
                bb = bf16x2_to_f2(pah[1]); pal[1] = pack_bf16x2(c2-bb.x, c3-bb.y);
                bb = bf16x2_to_f2(pah[2]); pal[2] = pack_bf16x2(d0-bb.x, d1-bb.y);
                bb = bf16x2_to_f2(pah[3]); pal[3] = pack_bf16x2(d2-bb.x, d3-bb.y);
            }
            uint32_t vfh[4][4], vfl[4][4];
            #pragma unroll
            for (int np = 0; np < 4; ++np) {
                uint32_t addr = bs + VH_OFF
                    + (np*16 + (lane & 7) + ((lane >> 4) << 3))*272
                    + j*32 + 16*((lane >> 3) & 1);
                ldsm4(vfh[np], addr);
                ldsm4(vfl[np], addr + (VL_OFF - VH_OFF));
            }
            #pragma unroll
            for (int np = 0; np < 4; ++np)
                #pragma unroll
                for (int sub = 0; sub < 2; ++sub) {
                    int nd = np*2 + sub;
                    mma_bf16(accO[nd], pah, &vfh[np][sub*2]);
                    mma_bf16(accO[nd], pal, &vfh[np][sub*2]);
                    mma_bf16(accO[nd], pah, &vfl[np][sub*2]);
                }
        }
        __syncthreads();
    }

    // ---- normalize + write O, stats ----
    const int b = bh >> 4, h = bh & 15;
    float inv0 = 1.f / rs0, inv1 = 1.f / rs1;
    int s0r = qrow0 + wid*16 + gid, s1r = s0r + 8;
    #pragma unroll
    for (int nd = 0; nd < 8; ++nd) {
        int d = nd*8 + qc*2;
        *(float2*)&g_ao[((size_t)(b*Ssz + s0r))*HIDsz + h*64 + d] =
            make_float2(accO[nd][0]*inv0, accO[nd][1]*inv0);
        *(float2*)&g_ao[((size_t)(b*Ssz + s1r))*HIDsz + h*64 + d] =
            make_float2(accO[nd][2]*inv1, accO[nd][3]*inv1);
    }
    if (qc == 0) {
        g_m[(size_t)bh*Ssz + s0r]   = rm0;  g_inv[(size_t)bh*Ssz + s0r] = inv0;
        g_m[(size_t)bh*Ssz + s1r]   = rm1;  g_inv[(size_t)bh*Ssz + s1r] = inv1;
    }
}

// ---------------- normalize attn ----------------
__global__ void __launch_bounds__(256) norm_kernel(float* __restrict__ attnp)
{
    const int row = blockIdx.x;
    const int bh  = blockIdx.y;
    const float m   = g_m[(size_t)bh*Ssz + row];
    const float inv = g_inv[(size_t)bh*Ssz + row];
    float* rowp = attnp + ((size_t)bh*Ssz + row)*Ssz;
    const int c = threadIdx.x << 3;
    #pragma unroll
    for (int u = 0; u < 2; ++u) {
        int c0 = c + u*4;
        if (c0 > row) {
            *(float4*)(rowp + c0) = make_float4(0.f, 0.f, 0.f, 0.f);
        } else {
            float4 s = *(const float4*)(rowp + c0);
            float4 p;
            p.x = expf(s.x - m) * inv;
            p.y = (c0+1 <= row) ? expf(s.y - m) * inv : 0.f;
            p.z = (c0+2 <= row) ? expf(s.z - m) * inv : 0.f;
            p.w = (c0+3 <= row) ? expf(s.w - m) * inv : 0.f;
            *(float4*)(rowp + c0) = p;
        }
    }
}

// ---------------- output projection (HMMA) ----------------
__global__ void __launch_bounds__(256) oproj_mma_kernel(
    const float* __restrict__ ob, float* __restrict__ outp)
{
    extern __shared__ char smem[];
    uint32_t smem_base = smem_u32(smem);
    const int tid = threadIdx.x;
    const int wid = tid >> 5, lane = tid & 31;
    const int warpM = wid >> 2, warpN = wid & 3;
    const int nBase = blockIdx.x * 128;
    const int mBase = blockIdx.y * 128;

    float acc[4][4][4] = {};
    gemm128(smem_base, g_aoh, g_aol, g_owh, g_owl, mBase, nBase, acc);

    #pragma unroll
    for (int mt = 0; mt < 4; ++mt) {
        int m0 = mBase + warpM*64 + mt*16 + (lane >> 2);
        #pragma unroll
        for (int nt = 0; nt < 4; ++nt) {
            int n = nBase + warpN*32 + nt*8 + 2*(lane & 3);
            float b0 = ob[n], b1 = ob[n+1];
            #pragma unroll
            for (int half = 0; half < 2; ++half) {
                int m = m0 + half*8;
                *(float2*)&outp[(size_t)m*HIDsz + n] = make_float2(
                    acc[mt][nt][half*2+0] + b0, acc[mt][nt][half*2+1] + b1);
            }
        }
    }
}

// ---------------- launch ----------------
extern "C" void kernel_launch(void* const* d_in, const int* in_sizes, int n_in,
                              void* d_out, int out_size)
{
    const float* x       = (const float*)d_in[0];
    const float* scaling = (const float*)d_in[2];
    const float* qw = (const float*)d_in[3];
    const float* qb = (const float*)d_in[4];
    const float* kw = (const float*)d_in[5];
    const float* kb = (const float*)d_in[6];
    const float* vw = (const float*)d_in[7];
    const float* vb = (const float*)d_in[8];
    const float* ow = (const float*)d_in[9];
    const float* ob = (const float*)d_in[10];

    const long long OUT_N  = (long long)Bsz*Ssz*HIDsz;
    const long long ATTN_N = (long long)Bsz*Hsz*Ssz*Ssz;

    float* outp  = (float*)d_out;
    float* attnp = 0;
    if ((long long)out_size >= OUT_N + ATTN_N) {
        attnp = (float*)d_out + OUT_N;
    } else if ((long long)out_size == ATTN_N) {
        attnp = (float*)d_out;
        void* p = 0;
        cudaGetSymbolAddress(&p, g_dummy_out);
        outp = (float*)p;
    }

    cudaFuncSetAttribute(qkv_mma_kernel, cudaFuncAttributeMaxDynamicSharedMemorySize, GEMM_SMEM);
    cudaFuncSetAttribute(oproj_mma_kernel, cudaFuncAttributeMaxDynamicSharedMemorySize, GEMM_SMEM);
    cudaFuncSetAttribute(attn_mma_kernel, cudaFuncAttributeMaxDynamicSharedMemorySize, ATTN_SMEM);

    void *xh, *xl, *wh, *wl, *owh_p, *owl_p, *aoh, *aol, *aop;
    cudaGetSymbolAddress(&xh, g_xh);   cudaGetSymbolAddress(&xl, g_xl);
    cudaGetSymbolAddress(&wh, g_wh);   cudaGetSymbolAddress(&wl, g_wl);
    cudaGetSymbolAddress(&owh_p, g_owh); cudaGetSymbolAddress(&owl_p, g_owl);
    cudaGetSymbolAddress(&aoh, g_aoh); cudaGetSymbolAddress(&aol, g_aol);
    cudaGetSymbolAddress(&aop, g_ao);

    const int N4_X = Msz*HIDsz/4;
    const int N4_W = HIDsz*HIDsz/4;

    cvt_split_kernel<<<(N4_X+255)/256, 256>>>(x, (__nv_bfloat16*)xh, (__nv_bfloat16*)xl, N4_X);
    cvt_split_kernel<<<(N4_W+255)/256, 256>>>(qw, (__nv_bfloat16*)wh, (__nv_bfloat16*)wl, N4_W);
    cvt_split_kernel<<<(N4_W+255)/256, 256>>>(kw, (__nv_bfloat16*)wh + (size_t)HIDsz*HIDsz,
                                              (__nv_bfloat16*)wl + (size_t)HIDsz*HIDsz, N4_W);
    cvt_split_kernel<<<(N4_W+255)/256, 256>>>(vw, (__nv_bfloat16*)wh + 2*(size_t)HIDsz*HIDsz,
                                              (__nv_bfloat16*)wl + 2*(size_t)HIDsz*HIDsz, N4_W);
    cvt_split_kernel<<<(N4_W+255)/256, 256>>>(ow, (__nv_bfloat16*)owh_p, (__nv_bfloat16*)owl_p, N4_W);
    pack_misc_kernel<<<12, 256>>>(qb, kb, vb, scaling);

    qkv_mma_kernel<<<dim3(24, 32), 256, GEMM_SMEM>>>();
    vt_cvt_kernel<<<dim3(16, 32), 256>>>();

    attn_mma_kernel<<<dim3(16, 32), 256, ATTN_SMEM>>>(attnp);
    if (attnp)
        norm_kernel<<<dim3(Ssz, BHsz), 256>>>(attnp);

    cvt_split_kernel<<<(N4_X+255)/256, 256>>>((const float*)aop,
                                              (__nv_bfloat16*)aoh, (__nv_bfloat16*)aol, N4_X);
    oproj_mma_kernel<<<dim3(HIDsz/128, Msz/128), 256, GEMM_SMEM>>>(ob, outp);
}

// round 9
// speedup vs baseline: 2.4636x; 1.0358x over previous
#include <cuda_runtime.h>
#include <cuda_bf16.h>
#include <math.h>
#include <stdint.h>

#define Bsz 2
#define Ssz 2048
#define HIDsz 1024
#define Hsz 16
#define Dsz 64
#define Msz (Bsz*Ssz)
#define BHsz (Bsz*Hsz)

// ---------------- scratch globals ----------------
__device__ float g_v[(size_t)BHsz*Ssz*Dsz];      // [B,H,S,D] fp32 (for transpose)
__device__ float g_dummy_out[(size_t)Bsz*Ssz*HIDsz];

__device__ __nv_bfloat16 g_qh[(size_t)BHsz*Ssz*Dsz], g_ql[(size_t)BHsz*Ssz*Dsz];
__device__ __nv_bfloat16 g_kh[(size_t)BHsz*Ssz*Dsz], g_kl[(size_t)BHsz*Ssz*Dsz];
__device__ __nv_bfloat16 g_vth[(size_t)BHsz*Dsz*Ssz], g_vtl[(size_t)BHsz*Dsz*Ssz]; // [bh][d][t]

__device__ __nv_bfloat16 g_xh[(size_t)Msz*HIDsz],  g_xl[(size_t)Msz*HIDsz];
__device__ __nv_bfloat16 g_wh[(size_t)3*HIDsz*HIDsz], g_wl[(size_t)3*HIDsz*HIDsz];
__device__ __nv_bfloat16 g_owh[(size_t)HIDsz*HIDsz],  g_owl[(size_t)HIDsz*HIDsz];
__device__ __nv_bfloat16 g_aoh[(size_t)Msz*HIDsz], g_aol[(size_t)Msz*HIDsz];
__device__ float g_bqkv[3*HIDsz];
__device__ float g_scale[Dsz];

// ---------------- helpers ----------------
__device__ __forceinline__ uint32_t smem_u32(const void* p) {
    uint32_t a;
    asm("{ .reg .u64 t; cvta.to.shared.u64 t, %1; cvt.u32.u64 %0, t; }" : "=r"(a) : "l"(p));
    return a;
}
__device__ __forceinline__ void cp16(uint32_t dst, const void* src) {
    asm volatile("cp.async.cg.shared.global [%0], [%1], 16;" :: "r"(dst), "l"(src));
}
__device__ __forceinline__ void ldsm4(uint32_t* r, uint32_t a) {
    asm volatile("ldmatrix.sync.aligned.m8n8.x4.shared.b16 {%0,%1,%2,%3}, [%4];"
        : "=r"(r[0]), "=r"(r[1]), "=r"(r[2]), "=r"(r[3]) : "r"(a));
}
__device__ __forceinline__ void mma_bf16(float* c, const uint32_t* a, const uint32_t* b) {
    asm volatile("mma.sync.aligned.m16n8k16.row.col.f32.bf16.bf16.f32 "
        "{%0,%1,%2,%3}, {%4,%5,%6,%7}, {%8,%9}, {%0,%1,%2,%3};"
        : "+f"(c[0]), "+f"(c[1]), "+f"(c[2]), "+f"(c[3])
        : "r"(a[0]), "r"(a[1]), "r"(a[2]), "r"(a[3]), "r"(b[0]), "r"(b[1]));
}
__device__ __forceinline__ uint32_t pack_bf16x2(float lo, float hi) {
    uint32_t r; asm("cvt.rn.bf16x2.f32 %0, %1, %2;" : "=r"(r) : "f"(hi), "f"(lo)); return r;
}
__device__ __forceinline__ float2 bf16x2_to_f2(uint32_t u) {
    float2 r;
    r.x = __uint_as_float(u << 16);
    r.y = __uint_as_float(u & 0xffff0000u);
    return r;
}

// ---------------- prepack: fp32 -> bf16 hi/lo ----------------
struct alignas(8) B4 { __nv_bfloat16 v[4]; };

__global__ void __launch_bounds__(256) cvt_split_kernel(
    const float* __restrict__ src, __nv_bfloat16* __restrict__ hi,
    __nv_bfloat16* __restrict__ lo, int n4)
{
    int i = blockIdx.x * 256 + threadIdx.x;
    if (i >= n4) return;
    float4 x = ((const float4*)src)[i];
    B4 h, l;
    float xs[4] = {x.x, x.y, x.z, x.w};
    #pragma unroll
    for (int j = 0; j < 4; ++j) {
        __nv_bfloat16 hb = __float2bfloat16_rn(xs[j]);
        h.v[j] = hb;
        l.v[j] = __float2bfloat16_rn(xs[j] - __bfloat162float(hb));
    }
    *(B4*)(hi + 4*(size_t)i) = h;
    *(B4*)(lo + 4*(size_t)i) = l;
}

__global__ void pack_misc_kernel(const float* qb, const float* kb, const float* vb,
                                 const float* scaling)
{
    int i = blockIdx.x * 256 + threadIdx.x;
    if (i < 1024)       g_bqkv[i] = qb[i];
    else if (i < 2048)  g_bqkv[i] = kb[i-1024];
    else if (i < 3072)  g_bqkv[i] = vb[i-2048];
    if (i < 64) {
        float sc = scaling[i];
        float sp = (sc > 20.f) ? sc : log1pf(expf(sc));
        g_scale[i] = sp * (1.442695040888963f * 0.125f);
    }
}

// ---------------- HMMA GEMM mainloop (dense projections) ----------------
#define PITCH   40
#define TILE_B  (128*PITCH*2)
#define STAGE_B (4*TILE_B)
#define GEMM_SMEM (2*STAGE_B)

__device__ __forceinline__ void gemm128(
    uint32_t smem_base,
    const __nv_bfloat16* __restrict__ Ah, const __nv_bfloat16* __restrict__ Al,
    const __nv_bfloat16* __restrict__ Bh, const __nv_bfloat16* __restrict__ Bl,
    int mBase, int nBase, float acc[4][4][4])
{
    const int tid  = threadIdx.x;
    const int wid  = tid >> 5, lane = tid & 31;
    const int warpM = wid >> 2, warpN = wid & 3;

    #define LOAD_CHUNK(ch) do {                                                 \
        const int st_ = (ch) & 1; const int kt_ = (ch) * 32;                    \
        uint32_t sb_ = smem_base + st_ * STAGE_B;                               \
        _Pragma("unroll")                                                       \
        for (int t_ = 0; t_ < 4; ++t_) {                                        \
            const __nv_bfloat16* src_ = t_==0?Ah:t_==1?Al:t_==2?Bh:Bl;          \
            int rowBase_ = (t_ < 2) ? mBase : nBase;                            \
            _Pragma("unroll")                                                   \
            for (int u_ = 0; u_ < 2; ++u_) {                                    \
                int idx_ = u_*256 + tid;                                        \
                int row_ = idx_ >> 2, cc_ = idx_ & 3;                           \
                cp16(sb_ + t_*TILE_B + row_*(PITCH*2) + cc_*16,                 \
                     src_ + (size_t)(rowBase_+row_)*HIDsz + kt_ + cc_*8);       \
            }                                                                   \
        }                                                                       \
        asm volatile("cp.async.commit_group;" ::: "memory");                    \
    } while (0)

    LOAD_CHUNK(0);
    for (int ch = 0; ch < 32; ++ch) {
        if (ch < 31) {
            LOAD_CHUNK(ch+1);
            asm volatile("cp.async.wait_group 1;" ::: "memory");
        } else {
            asm volatile("cp.async.wait_group 0;" ::: "memory");
        }
        __syncthreads();
        uint32_t sb = smem_base + (ch & 1) * STAGE_B;

        #pragma unroll
        for (int ks = 0; ks < 2; ++ks) {
            uint32_t ah[4][4], al[4][4], bh[2][4], bl[2][4];
            int acol = ks*32 + 16*(lane >> 4);
            int arow = warpM*64 + (lane & 15);
            #pragma unroll
            for (int mt = 0; mt < 4; ++mt)
                ldsm4(ah[mt], sb + 0*TILE_B + (arow + mt*16)*(PITCH*2) + acol);
            #pragma unroll
            for (int mt = 0; mt < 4; ++mt)
                ldsm4(al[mt], sb + 1*TILE_B + (arow + mt*16)*(PITCH*2) + acol);
            int bcol  = ks*32 + 16*((lane >> 3) & 1);
            int brow  = warpN*32 + (lane & 7) + ((lane >> 4) << 3);
            #pragma unroll
            for (int np = 0; np < 2; ++np) {
                ldsm4(bh[np], sb + 2*TILE_B + (brow + np*16)*(PITCH*2) + bcol);
                ldsm4(bl[np], sb + 3*TILE_B + (brow + np*16)*(PITCH*2) + bcol);
            }
            #pragma unroll
            for (int mt = 0; mt < 4; ++mt)
                #pragma unroll
                for (int nt = 0; nt < 4; ++nt) {
                    const uint32_t* bhp = &bh[nt >> 1][(nt & 1) * 2];
                    const uint32_t* blp = &bl[nt >> 1][(nt & 1) * 2];
                    mma_bf16(acc[mt][nt], ah[mt], bhp);
                    mma_bf16(acc[mt][nt], al[mt], bhp);
                    mma_bf16(acc[mt][nt], ah[mt], blp);
                }
        }
        __syncthreads();
    }
    #undef LOAD_CHUNK
}

// ---------------- QKV projection (HMMA) ----------------
__global__ void __launch_bounds__(256) qkv_mma_kernel()
{
    extern __shared__ char smem[];
    uint32_t smem_base = smem_u32(smem);
    const int tid = threadIdx.x;
    const int wid = tid >> 5, lane = tid & 31;
    const int warpM = wid >> 2, warpN = wid & 3;
    const int nBase = blockIdx.x * 128;
    const int mBase = blockIdx.y * 128;

    float acc[4][4][4] = {};
    gemm128(smem_base, g_xh, g_xl, g_wh, g_wl, mBase, nBase, acc);

    const int which = nBase >> 10;

    #pragma unroll
    for (int mt = 0; mt < 4; ++mt) {
        int m0 = mBase + warpM*64 + mt*16 + (lane >> 2);
        #pragma unroll
        for (int nt = 0; nt < 4; ++nt) {
            int nG = nBase + warpN*32 + nt*8 + 2*(lane & 3);
            int nl = nG & 1023, h = nl >> 6, d = nl & 63;
            float s0 = (which == 0) ? g_scale[d] : 1.f;
            float s1 = (which == 0) ? g_scale[d+1] : 1.f;
            float b0 = g_bqkv[nG], b1 = g_bqkv[nG+1];
            #pragma unroll
            for (int half = 0; half < 2; ++half) {
                int m = m0 + half*8;
                int b = m >> 11, s = m & 2047;
                float v0 = (acc[mt][nt][half*2+0] + b0) * s0;
                float v1 = (acc[mt][nt][half*2+1] + b1) * s1;
                size_t off = ((size_t)(b*Hsz + h)*Ssz + s)*Dsz + d;
                if (which == 2) {
                    *(float2*)&g_v[off] = make_float2(v0, v1);
                } else {
                    uint32_t hh = pack_bf16x2(v0, v1);
                    float2 bb = bf16x2_to_f2(hh);
                    uint32_t ll = pack_bf16x2(v0 - bb.x, v1 - bb.y);
                    if (which == 0) {
                        *(uint32_t*)&g_qh[off] = hh;
                        *(uint32_t*)&g_ql[off] = ll;
                    } else {
                        *(uint32_t*)&g_kh[off] = hh;
                        *(uint32_t*)&g_kl[off] = ll;
                    }
                }
            }
        }
    }
}

// ---------------- V transpose + split ----------------
__global__ void __launch_bounds__(256) vt_cvt_kernel()
{
    __shared__ float ts[128][65];
    const int bh = blockIdx.y, tB = blockIdx.x, tid = threadIdx.x;
    const float* src = g_v + ((size_t)bh*Ssz + tB*128)*Dsz;
    #pragma unroll
    for (int u = 0; u < 8; ++u) {
        int idx = u*256 + tid;
        int row = idx >> 4, c4 = (idx & 15) << 2;
        float4 v = *(const float4*)(src + row*64 + c4);
        ts[row][c4]=v.x; ts[row][c4+1]=v.y; ts[row][c4+2]=v.z; ts[row][c4+3]=v.w;
    }
    __syncthreads();
    #pragma unroll
    for (int u = 0; u < 16; ++u) {
        int idx = u*256 + tid;
        int d = idx >> 6, tp = idx & 63;
        float f0 = ts[tp*2][d], f1 = ts[tp*2+1][d];
        uint32_t h = pack_bf16x2(f0, f1);
        float2 hb = bf16x2_to_f2(h);
        uint32_t l = pack_bf16x2(f0 - hb.x, f1 - hb.y);
        size_t off = ((size_t)bh*Dsz + d)*Ssz + tB*128 + tp*2;
        *(uint32_t*)&g_vth[off] = h;
        *(uint32_t*)&g_vtl[off] = l;
    }
}

// ---------------- HMMA flash attention (two-pass, writes final probs) -----
#define QH_OFF 0
#define QL_OFF 18432
#define ST_OFF 36864
#define ST_STRIDE 71680
#define KH_OFF 0
#define KL_OFF 18432
#define VH_OFF 36864
#define VL_OFF 54272
#define ATTN_SMEM 180224

__global__ void __launch_bounds__(256) attn_mma_kernel(float* __restrict__ attnp)
{
    extern __shared__ char sm[];
    const uint32_t sb = smem_u32(sm);
    const int tid = threadIdx.x, wid = tid >> 5, lane = tid & 31;
    const int gid = lane >> 2, qc = lane & 3;
    const int qb = (int)(gridDim.x - 1) - (int)blockIdx.x;   // heavy first
    const int bh = blockIdx.y;
    const int qrow0 = qb * 128;

    const __nv_bfloat16* qhg = g_qh + ((size_t)bh*Ssz + qrow0)*Dsz;
    const __nv_bfloat16* qlg = g_ql + ((size_t)bh*Ssz + qrow0)*Dsz;
    const __nv_bfloat16* khg = g_kh + (size_t)bh*Ssz*Dsz;
    const __nv_bfloat16* klg = g_kl + (size_t)bh*Ssz*Dsz;
    const __nv_bfloat16* vhg = g_vth + (size_t)bh*Dsz*Ssz;
    const __nv_bfloat16* vlg = g_vtl + (size_t)bh*Dsz*Ssz;
    float* aBase = attnp ? (attnp + (size_t)bh*Ssz*Ssz) : (float*)0;

    // Q tile + K tile 0
    #pragma unroll
    for (int u = 0; u < 4; ++u) {
        int idx = u*256 + tid, row = idx >> 3, c = idx & 7;
        cp16(sb + QH_OFF + row*144 + c*16, qhg + (size_t)row*64 + c*8);
        cp16(sb + QL_OFF + row*144 + c*16, qlg + (size_t)row*64 + c*8);
    }
    #pragma unroll
    for (int u = 0; u < 4; ++u) {
        int idx = u*256 + tid, row = idx >> 3, c = idx & 7;
        cp16(sb + ST_OFF + KH_OFF + row*144 + c*16, khg + (size_t)row*64 + c*8);
        cp16(sb + ST_OFF + KL_OFF + row*144 + c*16, klg + (size_t)row*64 + c*8);
    }
    asm volatile("cp.async.commit_group;" ::: "memory");

    float rm0 = -INFINITY, rm1 = -INFINITY, rs0 = 0.f, rs1 = 0.f;
    uint32_t qfh[4][4], qfl[4][4];

    // ================= PASS 1: stats (K only) =================
    for (int tb = 0; tb <= qb; ++tb) {
        if (tb < qb) {
            const uint32_t bs2 = sb + ST_OFF + ((tb+1) & 1) * ST_STRIDE;
            const int t0 = (tb+1) * 128;
            #pragma unroll
            for (int u = 0; u < 4; ++u) {
                int idx = u*256 + tid, row = idx >> 3, c = idx & 7;
                cp16(bs2 + KH_OFF + row*144 + c*16, khg + (size_t)(t0+row)*64 + c*8);
                cp16(bs2 + KL_OFF + row*144 + c*16, klg + (size_t)(t0+row)*64 + c*8);
            }
            asm volatile("cp.async.commit_group;" ::: "memory");
            asm volatile("cp.async.wait_group 1;" ::: "memory");
        } else {
            asm volatile("cp.async.wait_group 0;" ::: "memory");
        }
        __syncthreads();

        if (tb == 0) {
            #pragma unroll
            for (int ks = 0; ks < 4; ++ks) {
                uint32_t a = sb + QH_OFF + (wid*16 + (lane & 15))*144 + ks*32 + 16*(lane >> 4);
                ldsm4(qfh[ks], a);
                ldsm4(qfl[ks], a + (QL_OFF - QH_OFF));
            }
        }
        const uint32_t bs = sb + ST_OFF + (tb & 1) * ST_STRIDE;

        float accS[16][4];
        #pragma unroll
        for (int nt = 0; nt < 16; ++nt)
            accS[nt][0] = accS[nt][1] = accS[nt][2] = accS[nt][3] = 0.f;

        #pragma unroll
        for (int ks = 0; ks < 4; ++ks) {
            #pragma unroll
            for (int nh = 0; nh < 2; ++nh) {
                uint32_t kfh[4][4], kfl[4][4];
                #pragma unroll
                for (int t4 = 0; t4 < 4; ++t4) {
                    uint32_t addr = bs + KH_OFF
                        + (nh*64 + t4*16 + (lane & 7) + ((lane >> 4) << 3))*144
                        + ks*32 + 16*((lane >> 3) & 1);
                    ldsm4(kfh[t4], addr);
                    ldsm4(kfl[t4], addr + (KL_OFF - KH_OFF));
                }
                #pragma unroll
                for (int t4 = 0; t4 < 4; ++t4)
                    #pragma unroll
                    for (int sub = 0; sub < 2; ++sub) {
                        int nt = nh*8 + t4*2 + sub;
                        mma_bf16(accS[nt], qfh[ks], &kfh[t4][sub*2]);
                        mma_bf16(accS[nt], qfl[ks], &kfh[t4][sub*2]);
                        mma_bf16(accS[nt], qfh[ks], &kfl[t4][sub*2]);
                    }
            }
        }
        if (tb == qb) {
            int rl0 = wid*16 + gid, rl1 = rl0 + 8;
            #pragma unroll
            for (int nt = 0; nt < 16; ++nt) {
                int c0 = nt*8 + qc*2;
                if (c0     > rl0) accS[nt][0] = -INFINITY;
                if (c0 + 1 > rl0) accS[nt][1] = -INFINITY;
                if (c0     > rl1) accS[nt][2] = -INFINITY;
                if (c0 + 1 > rl1) accS[nt][3] = -INFINITY;
            }
        }
        float m0 = -INFINITY, m1 = -INFINITY;
        #pragma unroll
        for (int nt = 0; nt < 16; ++nt) {
            m0 = fmaxf(m0, fmaxf(accS[nt][0], accS[nt][1]));
            m1 = fmaxf(m1, fmaxf(accS[nt][2], accS[nt][3]));
        }
        m0 = fmaxf(m0, __shfl_xor_sync(0xffffffffu, m0, 1));
        m0 = fmaxf(m0, __shfl_xor_sync(0xffffffffu, m0, 2));
        m1 = fmaxf(m1, __shfl_xor_sync(0xffffffffu, m1, 1));
        m1 = fmaxf(m1, __shfl_xor_sync(0xffffffffu, m1, 2));
        float nm0 = fmaxf(rm0, m0), nm1 = fmaxf(rm1, m1);
        float f0 = __expf(rm0 - nm0), f1 = __expf(rm1 - nm1);
        float s0 = 0.f, s1 = 0.f;
        #pragma unroll
        for (int nt = 0; nt < 16; ++nt) {
            s0 += __expf(accS[nt][0] - nm0) + __expf(accS[nt][1] - nm0);
            s1 += __expf(accS[nt][2] - nm1) + __expf(accS[nt][3] - nm1);
        }
        s0 += __shfl_xor_sync(0xffffffffu, s0, 1);
        s0 += __shfl_xor_sync(0xffffffffu, s0, 2);
        s1 += __shfl_xor_sync(0xffffffffu, s1, 1);
        s1 += __shfl_xor_sync(0xffffffffu, s1, 2);
        rs0 = rs0*f0 + s0;  rs1 = rs1*f1 + s1;
        rm0 = nm0;          rm1 = nm1;
        __syncthreads();
    }

    const float inv0 = 1.f / rs0, inv1 = 1.f / rs1;
    float accO[8][4] = {};

    // prime pass-2 tile 0 (K + V)
    #pragma unroll
    for (int u = 0; u < 4; ++u) {
        int idx = u*256 + tid, row = idx >> 3, c = idx & 7;
        cp16(sb + ST_OFF + KH_OFF + row*144 + c*16, khg + (size_t)row*64 + c*8);
        cp16(sb + ST_OFF + KL_OFF + row*144 + c*16, klg + (size_t)row*64 + c*8);
    }
    #pragma unroll
    for (int u = 0; u < 4; ++u) {
        int idx = u*256 + tid, d = idx >> 4, c = idx & 15;
        cp16(sb + ST_OFF + VH_OFF + d*272 + c*16, vhg + (size_t)d*Ssz + c*8);
        cp16(sb + ST_OFF + VL_OFF + d*272 + c*16, vlg + (size_t)d*Ssz + c*8);
    }
    asm volatile("cp.async.commit_group;" ::: "memory");

    // ================= PASS 2: probs + PV =================
    for (int tb = 0; tb <= qb; ++tb) {
        if (tb < qb) {
            const uint32_t bs2 = sb + ST_OFF + ((tb+1) & 1) * ST_STRIDE;
            const int t0 = (tb+1) * 128;
            #pragma unroll
            for (int u = 0; u < 4; ++u) {
                int idx = u*256 + tid, row = idx >> 3, c = idx & 7;
                cp16(bs2 + KH_OFF + row*144 + c*16, khg + (size_t)(t0+row)*64 + c*8);
                cp16(bs2 + KL_OFF + row*144 + c*16, klg + (size_t)(t0+row)*64 + c*8);
            }
            #pragma unroll
            for (int u = 0; u < 4; ++u) {
                int idx = u*256 + tid, d = idx >> 4, c = idx & 15;
                cp16(bs2 + VH_OFF + d*272 + c*16, vhg + (size_t)d*Ssz + t0 + c*8);
                cp16(bs2 + VL_OFF + d*272 + c*16, vlg + (size_t)d*Ssz + t0 + c*8);
            }
            asm volatile("cp.async.commit_group;" ::: "memory");
            asm volatile("cp.async.wait_group 1;" ::: "memory");
        } else {
            asm volatile("cp.async.wait_group 0;" ::: "memory");
        }
        __syncthreads();
        const uint32_t bs = sb + ST_OFF + (tb & 1) * ST_STRIDE;

        float accS[16][4];
        #pragma unroll
        for (int nt = 0; nt < 16; ++nt)
            accS[nt][0] = accS[nt][1] = accS[nt][2] = accS[nt][3] = 0.f;

        #pragma unroll
        for (int ks = 0; ks < 4; ++ks) {
            #pragma unroll
            for (int nh = 0; nh < 2; ++nh) {
                uint32_t kfh[4][4], kfl[4][4];
                #pragma unroll
                for (int t4 = 0; t4 < 4; ++t4) {
                    uint32_t addr = bs + KH_OFF
                        + (nh*64 + t4*16 + (lane & 7) + ((lane >> 4) << 3))*144
                        + ks*32 + 16*((lane >> 3) & 1);
                    ldsm4(kfh[t4], addr);
                    ldsm4(kfl[t4], addr + (KL_OFF - KH_OFF));
                }
                #pragma unroll
                for (int t4 = 0; t4 < 4; ++t4)
                    #pragma unroll
                    for (int sub = 0; sub < 2; ++sub) {
                        int nt = nh*8 + t4*2 + sub;
                        mma_bf16(accS[nt], qfh[ks], &kfh[t4][sub*2]);
                        mma_bf16(accS[nt], qfl[ks], &kfh[t4][sub*2]);
                        mma_bf16(accS[nt], qfh[ks], &kfl[t4][sub*2]);
                    }
            }
        }
        if (tb == qb) {
            int rl0 = wid*16 + gid, rl1 = rl0 + 8;
            #pragma unroll
            for (int nt = 0; nt < 16; ++nt) {
                int c0 = nt*8 + qc*2;
                if (c0     > rl0) accS[nt][0] = -INFINITY;
                if (c0 + 1 > rl0) accS[nt][1] = -INFINITY;
                if (c0     > rl1) accS[nt][2] = -INFINITY;
                if (c0 + 1 > rl1) accS[nt][3] = -INFINITY;
            }
        }

        // final normalized probabilities
        #pragma unroll
        for (int nt = 0; nt < 16; ++nt) {
            accS[nt][0] = __expf(accS[nt][0] - rm0) * inv0;
            accS[nt][1] = __expf(accS[nt][1] - rm0) * inv0;
            accS[nt][2] = __expf(accS[nt][2] - rm1) * inv1;
            accS[nt][3] = __expf(accS[nt][3] - rm1) * inv1;
        }
        if (aBase) {
            float* rp0 = aBase + (size_t)(qrow0 + wid*16 + gid)*Ssz + tb*128;
            float* rp1 = rp0 + (size_t)8*Ssz;
            #pragma unroll
            for (int nt = 0; nt < 16; ++nt) {
                int col = nt*8 + qc*2;
                *(float2*)(rp0 + col) = make_float2(accS[nt][0], accS[nt][1]);
                *(float2*)(rp1 + col) = make_float2(accS[nt][2], accS[nt][3]);
            }
        }

        // O += P V (split P in registers)
        #pragma unroll
        for (int j = 0; j < 8; ++j) {
            uint32_t pah[4], pal[4];
            {
                float c0 = accS[2*j][0],   c1 = accS[2*j][1];
                float c2 = accS[2*j][2],   c3 = accS[2*j][3];
                float d0 = accS[2*j+1][0], d1 = accS[2*j+1][1];
                float d2 = accS[2*j+1][2], d3 = accS[2*j+1][3];
                pah[0] = pack_bf16x2(c0, c1);  pah[1] = pack_bf16x2(c2, c3);
                pah[2] = pack_bf16x2(d0, d1);  pah[3] = pack_bf16x2(d2, d3);
                float2 bb;
                bb = bf16x2_to_f2(pah[0]); pal[0] = pack_bf16x2(c0-bb.x, c1-bb.y);
                bb = bf16x2_to_f2(pah[1]); pal[1] = pack_bf16x2(c2-bb.x, c3-bb.y);
                bb = bf16x2_to_f2(pah[2]); pal[2] = pack_bf16x2(d0-bb.x, d1-bb.y);
                bb = bf16x2_to_f2(pah[3]); pal[3] = pack_bf16x2(d2-bb.x, d3-bb.y);
            }
            uint32_t vfh[4][4], vfl[4][4];
            #pragma unroll
            for (int np = 0; np < 4; ++np) {
                uint32_t addr = bs + VH_OFF
                    + (np*16 + (lane & 7) + ((lane >> 4) << 3))*272
                    + j*32 + 16*((lane >> 3) & 1);
                ldsm4(vfh[np], addr);
                ldsm4(vfl[np], addr + (VL_OFF - VH_OFF));
            }
            #pragma unroll
            for (int np = 0; np < 4; ++np)
                #pragma unroll
                for (int sub = 0; sub < 2; ++sub) {
                    int nd = np*2 + sub;
                    mma_bf16(accO[nd], pah, &vfh[np][sub*2]);
                    mma_bf16(accO[nd], pal, &vfh[np][sub*2]);
                    mma_bf16(accO[nd], pah, &vfl[np][sub*2]);
                }
        }
        __syncthreads();
    }

    // zero upper-triangle tiles (balanced: heavy compute blocks zero fewer)
    if (aBase) {
        const float4 z4 = make_float4(0.f, 0.f, 0.f, 0.f);
        for (int tb2 = qb + 1; tb2 < Ssz/128; ++tb2) {
            float* tp = aBase + (size_t)qrow0*Ssz + tb2*128;
            #pragma unroll
            for (int u = 0; u < 16; ++u) {
                int idx = u*256 + tid;
                int row = idx >> 5, c = (idx & 31) << 2;
                *(float4*)(tp + (size_t)row*Ssz + c) = z4;
            }
        }
    }

    // write O as bf16 hi/lo planes (consumed directly by oproj)
    const int b = bh >> 4, h = bh & 15;
    int s0r = qrow0 + wid*16 + gid, s1r = s0r + 8;
    #pragma unroll
    for (int nd = 0; nd < 8; ++nd) {
        int d = nd*8 + qc*2;
        {
            float v0 = accO[nd][0], v1 = accO[nd][1];
            uint32_t hh = pack_bf16x2(v0, v1);
            float2 bb = bf16x2_to_f2(hh);
            uint32_t ll = pack_bf16x2(v0 - bb.x, v1 - bb.y);
            size_t off = ((size_t)(b*Ssz + s0r))*HIDsz + h*64 + d;
            *(uint32_t*)&g_aoh[off] = hh;
            *(uint32_t*)&g_aol[off] = ll;
        }
        {
            float v0 = accO[nd][2], v1 = accO[nd][3];
            uint32_t hh = pack_bf16x2(v0, v1);
            float2 bb = bf16x2_to_f2(hh);
            uint32_t ll = pack_bf16x2(v0 - bb.x, v1 - bb.y);
            size_t off = ((size_t)(b*Ssz + s1r))*HIDsz + h*64 + d;
            *(uint32_t*)&g_aoh[off] = hh;
            *(uint32_t*)&g_aol[off] = ll;
        }
    }
}

// ---------------- output projection (HMMA) ----------------
__global__ void __launch_bounds__(256) oproj_mma_kernel(
    const float* __restrict__ ob, float* __restrict__ outp)
{
    extern __shared__ char smem[];
    uint32_t smem_base = smem_u32(smem);
    const int tid = threadIdx.x;
    const int wid = tid >> 5, lane = tid & 31;
    const int warpM = wid >> 2, warpN = wid & 3;
    const int nBase = blockIdx.x * 128;
    const int mBase = blockIdx.y * 128;

    float acc[4][4][4] = {};
    gemm128(smem_base, g_aoh, g_aol, g_owh, g_owl, mBase, nBase, acc);

    #pragma unroll
    for (int mt = 0; mt < 4; ++mt) {
        int m0 = mBase + warpM*64 + mt*16 + (lane >> 2);
        #pragma unroll
        for (int nt = 0; nt < 4; ++nt) {
            int n = nBase + warpN*32 + nt*8 + 2*(lane & 3);
            float b0 = ob[n], b1 = ob[n+1];
            #pragma unroll
            for (int half = 0; half < 2; ++half) {
                int m = m0 + half*8;
                *(float2*)&outp[(size_t)m*HIDsz + n] = make_float2(
                    acc[mt][nt][half*2+0] + b0, acc[mt][nt][half*2+1] + b1);
            }
        }
    }
}

// ---------------- launch ----------------
extern "C" void kernel_launch(void* const* d_in, const int* in_sizes, int n_in,
                              void* d_out, int out_size)
{
    const float* x       = (const float*)d_in[0];
    const float* scaling = (const float*)d_in[2];
    const float* qw = (const float*)d_in[3];
    const float* qb = (const float*)d_in[4];
    const float* kw = (const float*)d_in[5];
    const float* kb = (const float*)d_in[6];
    const float* vw = (const float*)d_in[7];
    const float* vb = (const float*)d_in[8];
    const float* ow = (const float*)d_in[9];
    const float* ob = (const float*)d_in[10];

    const long long OUT_N  = (long long)Bsz*Ssz*HIDsz;
    const long long ATTN_N = (long long)Bsz*Hsz*Ssz*Ssz;

    float* outp  = (float*)d_out;
    float* attnp = 0;
    if ((long long)out_size >= OUT_N + ATTN_N) {
        attnp = (float*)d_out + OUT_N;
    } else if ((long long)out_size == ATTN_N) {
        attnp = (float*)d_out;
        void* p = 0;
        cudaGetSymbolAddress(&p, g_dummy_out);
        outp = (float*)p;
    }

    cudaFuncSetAttribute(qkv_mma_kernel, cudaFuncAttributeMaxDynamicSharedMemorySize, GEMM_SMEM);
    cudaFuncSetAttribute(oproj_mma_kernel, cudaFuncAttributeMaxDynamicSharedMemorySize, GEMM_SMEM);
    cudaFuncSetAttribute(attn_mma_kernel, cudaFuncAttributeMaxDynamicSharedMemorySize, ATTN_SMEM);

    void *xh, *xl, *wh, *wl, *owh_p, *owl_p;
    cudaGetSymbolAddress(&xh, g_xh);   cudaGetSymbolAddress(&xl, g_xl);
    cudaGetSymbolAddress(&wh, g_wh);   cudaGetSymbolAddress(&wl, g_wl);
    cudaGetSymbolAddress(&owh_p, g_owh); cudaGetSymbolAddress(&owl_p, g_owl);

    const int N4_X = Msz*HIDsz/4;
    const int N4_W = HIDsz*HIDsz/4;

    cvt_split_kernel<<<(N4_X+255)/256, 256>>>(x, (__nv_bfloat16*)xh, (__nv_bfloat16*)xl, N4_X);
    cvt_split_kernel<<<(N4_W+255)/256, 256>>>(qw, (__nv_bfloat16*)wh, (__nv_bfloat16*)wl, N4_W);
    cvt_split_kernel<<<(N4_W+255)/256, 256>>>(kw, (__nv_bfloat16*)wh + (size_t)HIDsz*HIDsz,
                                              (__nv_bfloat16*)wl + (size_t)HIDsz*HIDsz, N4_W);
    cvt_split_kernel<<<(N4_W+255)/256, 256>>>(vw, (__nv_bfloat16*)wh + 2*(size_t)HIDsz*HIDsz,
                                              (__nv_bfloat16*)wl + 2*(size_t)HIDsz*HIDsz, N4_W);
    cvt_split_kernel<<<(N4_W+255)/256, 256>>>(ow, (__nv_bfloat16*)owh_p, (__nv_bfloat16*)owl_p, N4_W);
    pack_misc_kernel<<<12, 256>>>(qb, kb, vb, scaling);

    qkv_mma_kernel<<<dim3(24, 32), 256, GEMM_SMEM>>>();
    vt_cvt_kernel<<<dim3(16, 32), 256>>>();

    attn_mma_kernel<<<dim3(16, 32), 256, ATTN_SMEM>>>(attnp);

    oproj_mma_kernel<<<dim3(HIDsz/128, Msz/128), 256, GEMM_SMEM>>>(ob, outp);
}